// round 1
// baseline (speedup 1.0000x reference)
#include <cuda_runtime.h>
#include <math.h>

#define BB   8
#define NN   2048
#define LL   4096
#define CC   128
#define KNB  8
#define FFD  512
#define RR2  0.04f

// ---------------- scratch (device globals; no runtime allocation) ----------
__device__ int   g_idx [BB*NN*KNB];
__device__ int   g_cnt [BB*NN];
__device__ float g_asrc[(size_t)BB*LL*CC];
__device__ float g_v   [(size_t)BB*LL*CC];
__device__ float g_ai  [(size_t)BB*NN*CC];
__device__ float g_h   [(size_t)BB*NN*FFD];

// ---------------- kNN radius search ---------------------------------------
// grid (B, N/128), block 128. Whole batch kv_xyz (48KB) + pad (4KB) in SMEM.
__global__ __launch_bounds__(128) void knn_kernel(
    const float* __restrict__ qxyz, const float* __restrict__ kxyz,
    const unsigned char* __restrict__ kpad,
    int* __restrict__ gidx, int* __restrict__ gcnt)
{
    extern __shared__ float sh[];
    float* sx = sh;                               // [3*LL]
    unsigned char* sp = (unsigned char*)(sh + 3*LL);

    const int b = blockIdx.x;
    for (int i = threadIdx.x; i < 3*LL; i += blockDim.x)
        sx[i] = kxyz[(size_t)b*3*LL + i];
    for (int i = threadIdx.x; i < LL; i += blockDim.x)
        sp[i] = kpad[(size_t)b*LL + i];
    __syncthreads();

    const int q = blockIdx.y * blockDim.x + threadIdx.x;
    const float qx = qxyz[((size_t)b*NN + q)*3 + 0];
    const float qy = qxyz[((size_t)b*NN + q)*3 + 1];
    const float qz = qxyz[((size_t)b*NN + q)*3 + 2];

    float bd[KNB]; int bi[KNB];
#pragma unroll
    for (int k = 0; k < KNB; k++) { bd[k] = 1e30f; bi[k] = 0; }

    for (int j = 0; j < LL; j++) {
        float dx = sx[3*j+0] - qx;
        float dy = sx[3*j+1] - qy;
        float dz = sx[3*j+2] - qz;
        float d2 = fmaf(dx, dx, fmaf(dy, dy, dz*dz));
        if (d2 <= RR2 && d2 < bd[KNB-1] && !sp[j]) {
            float v = d2; int vi = j;
#pragma unroll
            for (int k = 0; k < KNB; k++) {
                if (v < bd[k]) {
                    float tf = bd[k]; bd[k] = v; v = tf;
                    int   ti = bi[k]; bi[k] = vi; vi = ti;
                }
            }
        }
    }
    int cnt = 0;
#pragma unroll
    for (int k = 0; k < KNB; k++) cnt += (bd[k] <= RR2) ? 1 : 0;
#pragma unroll
    for (int k = 0; k < KNB; k++)
        gidx[((size_t)b*NN + q)*KNB + k] = bi[k];
    gcnt[b*NN + q] = cnt;
}

// ---------------- generic fp32 GEMM: C = epi(A[M,KD] @ W[KD,Ncols] + bias) -
// block tile 64x128, 256 threads, thread tile 4x8.
// EPI: 0 = (+bias), 1 = (+bias, exact GELU), 2 = (+bias, +resid, LayerNorm)
template<int KD, int EPI>
__global__ __launch_bounds__(256) void gemm_kernel(
    const float* __restrict__ A, const float* __restrict__ W,
    const float* __restrict__ bias, float* __restrict__ Cout, int Ncols,
    const float* __restrict__ resid,
    const float* __restrict__ lng, const float* __restrict__ lnb)
{
    __shared__ float smem[8192];
    float* As = smem;           // [32][64] k-major
    float* Ws = smem + 2048;    // [32][128]

    const int m0 = blockIdx.x * 64;
    const int n0 = blockIdx.y * 128;
    const int tid = threadIdx.x;
    const int tx = tid & 15, ty = tid >> 4;

    float acc[4][8];
#pragma unroll
    for (int i = 0; i < 4; i++)
#pragma unroll
        for (int j = 0; j < 8; j++) acc[i][j] = 0.f;

    for (int kc = 0; kc < KD; kc += 32) {
#pragma unroll
        for (int r = 0; r < 2; r++) {
            int id  = tid + r*256;
            int row = id >> 3, c4 = (id & 7) * 4;
            float4 v = *(const float4*)&A[(size_t)(m0+row)*KD + kc + c4];
            As[(c4+0)*64 + row] = v.x;
            As[(c4+1)*64 + row] = v.y;
            As[(c4+2)*64 + row] = v.z;
            As[(c4+3)*64 + row] = v.w;
        }
#pragma unroll
        for (int r = 0; r < 4; r++) {
            int id  = tid + r*256;
            int row = id >> 5, c4 = (id & 31) * 4;
            *(float4*)&Ws[row*128 + c4] =
                *(const float4*)&W[(size_t)(kc+row)*Ncols + n0 + c4];
        }
        __syncthreads();
#pragma unroll
        for (int kk = 0; kk < 32; kk++) {
            float4 a4 = *(const float4*)&As[kk*64 + ty*4];
            float4 w0 = *(const float4*)&Ws[kk*128 + tx*8];
            float4 w1 = *(const float4*)&Ws[kk*128 + tx*8 + 4];
            float av[4] = {a4.x, a4.y, a4.z, a4.w};
            float wv[8] = {w0.x,w0.y,w0.z,w0.w,w1.x,w1.y,w1.z,w1.w};
#pragma unroll
            for (int i = 0; i < 4; i++)
#pragma unroll
                for (int j = 0; j < 8; j++)
                    acc[i][j] = fmaf(av[i], wv[j], acc[i][j]);
        }
        __syncthreads();
    }

    if (EPI != 2) {
#pragma unroll
        for (int i = 0; i < 4; i++) {
            int row = m0 + ty*4 + i;
            float o[8];
#pragma unroll
            for (int j = 0; j < 8; j++) {
                int c = n0 + tx*8 + j;
                float v = acc[i][j] + (bias ? bias[c] : 0.f);
                if (EPI == 1) v = 0.5f * v * (1.f + erff(v * 0.70710678118654752f));
                o[j] = v;
            }
            float4 s0 = make_float4(o[0],o[1],o[2],o[3]);
            float4 s1 = make_float4(o[4],o[5],o[6],o[7]);
            *(float4*)&Cout[(size_t)row*Ncols + n0 + tx*8]     = s0;
            *(float4*)&Cout[(size_t)row*Ncols + n0 + tx*8 + 4] = s1;
        }
    } else {
        // residual + LayerNorm epilogue (Ncols == 128, n0 == 0)
        float* Cs = smem;  // reuse: [64][128]
#pragma unroll
        for (int i = 0; i < 4; i++) {
            int lr = ty*4 + i, grow = m0 + lr;
#pragma unroll
            for (int j = 0; j < 8; j++) {
                int c = tx*8 + j;
                Cs[lr*128 + c] = acc[i][j] + bias[c] + resid[(size_t)grow*128 + c];
            }
        }
        __syncthreads();
        const int wid = tid >> 5, lane = tid & 31;
#pragma unroll
        for (int rr = 0; rr < 8; rr++) {
            int lr = wid*8 + rr;
            float xv[4]; float s = 0.f;
#pragma unroll
            for (int t = 0; t < 4; t++) { xv[t] = Cs[lr*128 + lane + t*32]; s += xv[t]; }
#pragma unroll
            for (int o = 16; o; o >>= 1) s += __shfl_xor_sync(0xffffffffu, s, o);
            float mu = s * (1.f/128.f);
            float vs = 0.f;
#pragma unroll
            for (int t = 0; t < 4; t++) { float d = xv[t]-mu; vs += d*d; }
#pragma unroll
            for (int o = 16; o; o >>= 1) vs += __shfl_xor_sync(0xffffffffu, vs, o);
            float rstd = rsqrtf(vs * (1.f/128.f) + 1e-5f);
            int grow = m0 + lr;
#pragma unroll
            for (int t = 0; t < 4; t++) {
                int c = lane + t*32;
                Cout[(size_t)grow*128 + c] = (xv[t]-mu)*rstd*lng[c] + lnb[c];
            }
        }
    }
}

// ---------------- fused attention block ------------------------------------
// One block = 16 queries = 128 edges. Builds D=(ai-aj) in SMEM, 128^3 GEMM
// with W_attn, relu+bias, per-channel masked softmax over K, V-gather
// weighted sum, residual + LayerNorm. 256 threads.
__global__ __launch_bounds__(256) void attn_kernel(
    const float* __restrict__ ai,   const float* __restrict__ asrc,
    const float* __restrict__ V,    const int*   __restrict__ gidx,
    const int*   __restrict__ gcnt, const float* __restrict__ Wat,
    const float* __restrict__ bat,  float* __restrict__ out,
    const float* __restrict__ g1,   const float* __restrict__ b1)
{
    extern __shared__ float sm[];
    float* sD   = sm;                    // [128][132]  (D, then reused as logits)
    float* sW   = sm + 128*132;          // [32][128]
    int*   snid = (int*)(sW + 32*128);   // [128]
    int*   scnt = snid + 128;            // [16]

    const int tid = threadIdx.x;
    const int q0  = blockIdx.x * 16;     // global query row (over B*N)
    const int b   = q0 / NN;

    if (tid < 128) snid[tid] = gidx[(size_t)q0*KNB + tid];
    if (tid < 16)  scnt[tid] = gcnt[q0 + tid];
    __syncthreads();

    // build D (k-major): sD[c][e] = ai[q][c] - asrc[nid][c]
    {
        int e = tid >> 1, half = tid & 1;
        int q = e >> 3;
        int nid = snid[e];
        const float4* arow = (const float4*)(ai   + ((size_t)(q0+q))*CC + half*64);
        const float4* srow = (const float4*)(asrc + ((size_t)b*LL + nid)*CC + half*64);
#pragma unroll
        for (int i = 0; i < 16; i++) {
            float4 av = arow[i], sv = srow[i];
            int c = half*64 + i*4;
            sD[(c+0)*132 + e] = av.x - sv.x;
            sD[(c+1)*132 + e] = av.y - sv.y;
            sD[(c+2)*132 + e] = av.z - sv.z;
            sD[(c+3)*132 + e] = av.w - sv.w;
        }
    }

    const int tx = tid & 15, ty = tid >> 4;
    float acc[8][8];
#pragma unroll
    for (int i = 0; i < 8; i++)
#pragma unroll
        for (int j = 0; j < 8; j++) acc[i][j] = 0.f;

    for (int kc = 0; kc < 128; kc += 32) {
#pragma unroll
        for (int r = 0; r < 4; r++) {
            int id = tid + r*256;
            int row = id >> 5, c4 = (id & 31) * 4;
            *(float4*)&sW[row*128 + c4] =
                *(const float4*)&Wat[(size_t)(kc+row)*CC + c4];
        }
        __syncthreads();
#pragma unroll
        for (int kk = 0; kk < 32; kk++) {
            const float* dp = &sD[(kc+kk)*132 + ty*8];
            float4 a0 = *(const float4*)dp;
            float4 a1 = *(const float4*)(dp + 4);
            float4 w0 = *(const float4*)&sW[kk*128 + tx*8];
            float4 w1 = *(const float4*)&sW[kk*128 + tx*8 + 4];
            float av[8] = {a0.x,a0.y,a0.z,a0.w,a1.x,a1.y,a1.z,a1.w};
            float wv[8] = {w0.x,w0.y,w0.z,w0.w,w1.x,w1.y,w1.z,w1.w};
#pragma unroll
            for (int i = 0; i < 8; i++)
#pragma unroll
                for (int j = 0; j < 8; j++)
                    acc[i][j] = fmaf(av[i], wv[j], acc[i][j]);
        }
        __syncthreads();
    }

    // logits = relu(acc + bias), stored e-major into sD: sD[e][c]
    {
        float bb[8];
#pragma unroll
        for (int j = 0; j < 8; j++) bb[j] = bat[tx*8 + j];
#pragma unroll
        for (int i = 0; i < 8; i++) {
            int e = ty*8 + i;
            float4 o0, o1;
            o0.x = fmaxf(acc[i][0]+bb[0], 0.f);
            o0.y = fmaxf(acc[i][1]+bb[1], 0.f);
            o0.z = fmaxf(acc[i][2]+bb[2], 0.f);
            o0.w = fmaxf(acc[i][3]+bb[3], 0.f);
            o1.x = fmaxf(acc[i][4]+bb[4], 0.f);
            o1.y = fmaxf(acc[i][5]+bb[5], 0.f);
            o1.z = fmaxf(acc[i][6]+bb[6], 0.f);
            o1.w = fmaxf(acc[i][7]+bb[7], 0.f);
            *(float4*)&sD[e*132 + tx*8]     = o0;
            *(float4*)&sD[e*132 + tx*8 + 4] = o1;
        }
    }
    __syncthreads();

    // softmax over valid k per channel + V gather + residual + LN
    {
        const int q  = tid >> 4;
        const int c0 = (tid & 15) * 8;
        const int kcnt = scnt[q];

        float mx[8], sum[8], upd[8];
#pragma unroll
        for (int j = 0; j < 8; j++) { mx[j] = -1e30f; sum[j] = 0.f; upd[j] = 0.f; }

        for (int k = 0; k < kcnt; k++) {
#pragma unroll
            for (int j = 0; j < 8; j++)
                mx[j] = fmaxf(mx[j], sD[(q*8+k)*132 + c0 + j]);
        }
        for (int k = 0; k < kcnt; k++) {
            int nid = snid[q*8 + k];
            const float4* vr = (const float4*)(V + ((size_t)b*LL + nid)*CC + c0);
            float4 v0 = vr[0], v1 = vr[1];
            float vv[8] = {v0.x,v0.y,v0.z,v0.w,v1.x,v1.y,v1.z,v1.w};
#pragma unroll
            for (int j = 0; j < 8; j++) {
                float w = expf(sD[(q*8+k)*132 + c0 + j] - mx[j]);
                sum[j] += w;
                upd[j] = fmaf(w, vv[j], upd[j]);
            }
        }
#pragma unroll
        for (int j = 0; j < 8; j++) upd[j] /= fmaxf(sum[j], 1e-9f);

        // residual + LayerNorm (16 lanes per query within a warp)
        float x[8]; float s = 0.f;
        const float* orow = out + (size_t)(q0+q)*CC + c0;
#pragma unroll
        for (int j = 0; j < 8; j++) { x[j] = orow[j] + upd[j]; s += x[j]; }
#pragma unroll
        for (int o = 8; o; o >>= 1) s += __shfl_xor_sync(0xffffffffu, s, o);
        float mu = s * (1.f/128.f);
        float vs = 0.f;
#pragma unroll
        for (int j = 0; j < 8; j++) { float d = x[j]-mu; vs += d*d; }
#pragma unroll
        for (int o = 8; o; o >>= 1) vs += __shfl_xor_sync(0xffffffffu, vs, o);
        float rstd = rsqrtf(vs * (1.f/128.f) + 1e-5f);

        float y[8];
#pragma unroll
        for (int j = 0; j < 8; j++)
            y[j] = (x[j]-mu)*rstd*g1[c0+j] + b1[c0+j];
        float4 s0 = make_float4(y[0],y[1],y[2],y[3]);
        float4 s1 = make_float4(y[4],y[5],y[6],y[7]);
        *(float4*)&out[(size_t)(q0+q)*CC + c0]     = s0;
        *(float4*)&out[(size_t)(q0+q)*CC + c0 + 4] = s1;
    }
}

// ---------------- launch ----------------------------------------------------
extern "C" void kernel_launch(void* const* d_in, const int* in_sizes, int n_in,
                              void* d_out, int out_size)
{
    const float*         q_xyz  = (const float*)d_in[0];
    const float*         q_feat = (const float*)d_in[1];
    const float*         kv_xyz = (const float*)d_in[2];
    const float*         kv_feat= (const float*)d_in[3];
    const unsigned char* kv_pad = (const unsigned char*)d_in[4];
    const float* W_lin  = (const float*)d_in[5];
    const float* b_lin  = (const float*)d_in[6];
    const float* W_src  = (const float*)d_in[7];
    const float* W_dst  = (const float*)d_in[8];
    const float* W_attn = (const float*)d_in[9];
    const float* b_attn = (const float*)d_in[10];
    const float* ln1_g  = (const float*)d_in[11];
    const float* ln1_b  = (const float*)d_in[12];
    const float* W_ff1  = (const float*)d_in[13];
    const float* b_ff1  = (const float*)d_in[14];
    const float* W_ff2  = (const float*)d_in[15];
    const float* b_ff2  = (const float*)d_in[16];
    const float* ln2_g  = (const float*)d_in[17];
    const float* ln2_b  = (const float*)d_in[18];
    float* out = (float*)d_out;

    void *p_idx, *p_cnt, *p_asrc, *p_v, *p_ai, *p_h;
    cudaGetSymbolAddress(&p_idx,  g_idx);
    cudaGetSymbolAddress(&p_cnt,  g_cnt);
    cudaGetSymbolAddress(&p_asrc, g_asrc);
    cudaGetSymbolAddress(&p_v,    g_v);
    cudaGetSymbolAddress(&p_ai,   g_ai);
    cudaGetSymbolAddress(&p_h,    g_h);
    int*   idx_p  = (int*)p_idx;
    int*   cnt_p  = (int*)p_cnt;
    float* asrc_p = (float*)p_asrc;
    float* v_p    = (float*)p_v;
    float* ai_p   = (float*)p_ai;
    float* h_p    = (float*)p_h;

    const int KNN_SMEM  = 3*LL*4 + LL;                       // 53248
    const int ATTN_SMEM = (128*132 + 32*128)*4 + 128*4 + 16*4; // 84544
    cudaFuncSetAttribute(knn_kernel,  cudaFuncAttributeMaxDynamicSharedMemorySize, KNN_SMEM);
    cudaFuncSetAttribute(attn_kernel, cudaFuncAttributeMaxDynamicSharedMemorySize, ATTN_SMEM);

    // out = q_feat
    cudaMemcpyAsync(out, q_feat, (size_t)BB*NN*CC*sizeof(float),
                    cudaMemcpyDeviceToDevice, 0);

    // radius kNN (once; shared across layers)
    knn_kernel<<<dim3(BB, NN/128), 128, KNN_SMEM>>>(q_xyz, kv_xyz, kv_pad, idx_p, cnt_p);

    const int BL = BB*LL;   // 32768
    const int BN = BB*NN;   // 16384

    for (int l = 0; l < 2; l++) {
        const size_t oCC  = (size_t)l * CC * CC;
        const size_t oC   = (size_t)l * CC;
        const size_t oF1  = (size_t)l * CC * FFD;
        const size_t oF   = (size_t)l * FFD;
        const size_t oF2  = (size_t)l * FFD * CC;

        // kv projections: Asrc = kv_feat @ W_src ; V = kv_feat @ W_lin + b_lin
        gemm_kernel<128,0><<<dim3(BL/64,1), 256>>>(
            kv_feat, W_src + oCC, nullptr, asrc_p, CC, nullptr, nullptr, nullptr);
        gemm_kernel<128,0><<<dim3(BL/64,1), 256>>>(
            kv_feat, W_lin + oCC, b_lin + oC, v_p, CC, nullptr, nullptr, nullptr);
        // ai = out @ W_dst
        gemm_kernel<128,0><<<dim3(BN/64,1), 256>>>(
            out, W_dst + oCC, nullptr, ai_p, CC, nullptr, nullptr, nullptr);
        // fused attention + residual + LN1
        attn_kernel<<<BN/16, 256, ATTN_SMEM>>>(
            ai_p, asrc_p, v_p, idx_p, cnt_p,
            W_attn + oCC, b_attn + oC, out, ln1_g + oC, ln1_b + oC);
        // h = gelu(out @ W_ff1 + b_ff1)
        gemm_kernel<128,1><<<dim3(BN/64,4), 256>>>(
            out, W_ff1 + oF1, b_ff1 + oF, h_p, FFD, nullptr, nullptr, nullptr);
        // out = LN2(out + h @ W_ff2 + b_ff2)
        gemm_kernel<512,2><<<dim3(BN/64,1), 256>>>(
            h_p, W_ff2 + oF2, b_ff2 + oC, out, CC, out, ln2_g + oC, ln2_b + oC);
    }
}

// round 2
// speedup vs baseline: 1.8156x; 1.8156x over previous
#include <cuda_runtime.h>
#include <math.h>
#include <stdint.h>

#define BB   8
#define NN   2048
#define LL   4096
#define CC   128
#define KNB  8
#define FFD  512
#define RR2  0.04f

// ---------------- scratch (device globals; no runtime allocation) ----------
__device__ int   g_idx [BB*NN*KNB];
__device__ int   g_cnt [BB*NN];
__device__ float g_asrc[(size_t)BB*LL*CC];
__device__ float g_v   [(size_t)BB*LL*CC];
__device__ float g_ai  [(size_t)BB*NN*CC];
__device__ float g_h   [(size_t)BB*NN*FFD];

__device__ __forceinline__ float to_tf32(float x) {
    float r;
    asm("cvt.rna.tf32.f32 %0, %1;" : "=f"(r) : "f"(x));
    return r;
}

__device__ __forceinline__ void mma_tf32(float* c, const uint32_t* a,
                                         uint32_t b0, uint32_t b1) {
    asm volatile(
        "mma.sync.aligned.m16n8k8.row.col.f32.tf32.tf32.f32 "
        "{%0,%1,%2,%3}, {%4,%5,%6,%7}, {%8,%9}, {%0,%1,%2,%3};"
        : "+f"(c[0]), "+f"(c[1]), "+f"(c[2]), "+f"(c[3])
        : "r"(a[0]), "r"(a[1]), "r"(a[2]), "r"(a[3]), "r"(b0), "r"(b1));
}

// ---------------- kNN radius search ---------------------------------------
__global__ __launch_bounds__(128) void knn_kernel(
    const float* __restrict__ qxyz, const float* __restrict__ kxyz,
    const unsigned char* __restrict__ kpad,
    int* __restrict__ gidx, int* __restrict__ gcnt)
{
    extern __shared__ float sh[];
    float* sx = sh;                               // [3*LL]
    unsigned char* sp = (unsigned char*)(sh + 3*LL);

    const int b = blockIdx.x;
    for (int i = threadIdx.x; i < 3*LL; i += blockDim.x)
        sx[i] = kxyz[(size_t)b*3*LL + i];
    for (int i = threadIdx.x; i < LL; i += blockDim.x)
        sp[i] = kpad[(size_t)b*LL + i];
    __syncthreads();

    const int q = blockIdx.y * blockDim.x + threadIdx.x;
    const float qx = qxyz[((size_t)b*NN + q)*3 + 0];
    const float qy = qxyz[((size_t)b*NN + q)*3 + 1];
    const float qz = qxyz[((size_t)b*NN + q)*3 + 2];

    float bd[KNB]; int bi[KNB];
#pragma unroll
    for (int k = 0; k < KNB; k++) { bd[k] = 1e30f; bi[k] = 0; }

    for (int j = 0; j < LL; j++) {
        float dx = sx[3*j+0] - qx;
        float dy = sx[3*j+1] - qy;
        float dz = sx[3*j+2] - qz;
        float d2 = fmaf(dx, dx, fmaf(dy, dy, dz*dz));
        if (d2 <= RR2 && d2 < bd[KNB-1] && !sp[j]) {
            float v = d2; int vi = j;
#pragma unroll
            for (int k = 0; k < KNB; k++) {
                if (v < bd[k]) {
                    float tf = bd[k]; bd[k] = v; v = tf;
                    int   ti = bi[k]; bi[k] = vi; vi = ti;
                }
            }
        }
    }
    int cnt = 0;
#pragma unroll
    for (int k = 0; k < KNB; k++) cnt += (bd[k] <= RR2) ? 1 : 0;
#pragma unroll
    for (int k = 0; k < KNB; k++)
        gidx[((size_t)b*NN + q)*KNB + k] = bi[k];
    gcnt[b*NN + q] = cnt;
}

// ---------------- tf32 tensor-core GEMM -------------------------------------
// C = epi(A[M,KD] @ W[KD,Ncols] + bias). Block tile 128x128, 8 warps (4x2),
// warp tile 32x64 via m16n8k8 tf32 mma.
// EPI: 0 = (+bias), 1 = (+bias, exact GELU), 2 = (+bias, +resid, LayerNorm)
template<int KD, int EPI>
__global__ __launch_bounds__(256) void gemm_mma(
    const float* __restrict__ A, const float* __restrict__ W,
    const float* __restrict__ bias, float* __restrict__ Cout, int Ncols,
    const float* __restrict__ resid,
    const float* __restrict__ lng, const float* __restrict__ lnb)
{
    __shared__ float As[128*36];
    __shared__ float Ws[32*132];
    __shared__ float rs1[128], rs2[128];

    const int m0 = blockIdx.x * 128;
    const int n0 = blockIdx.y * 128;
    const int tid = threadIdx.x;
    const int lane = tid & 31, warp = tid >> 5;
    const int wm = (warp & 3) * 32, wn = (warp >> 2) * 64;
    const int gID = lane >> 2, tig = lane & 3;

    if (EPI == 2 && tid < 128) { rs1[tid] = 0.f; rs2[tid] = 0.f; }

    float acc[2][8][4];
#pragma unroll
    for (int mt = 0; mt < 2; mt++)
#pragma unroll
        for (int nt = 0; nt < 8; nt++)
#pragma unroll
            for (int c = 0; c < 4; c++) acc[mt][nt][c] = 0.f;

    for (int kc = 0; kc < KD; kc += 32) {
#pragma unroll
        for (int r = 0; r < 4; r++) {
            int id = tid + r*256;
            int row = id >> 3, c4 = (id & 7) * 4;
            float4 v = *(const float4*)&A[(size_t)(m0+row)*KD + kc + c4];
            As[row*36 + c4+0] = to_tf32(v.x);
            As[row*36 + c4+1] = to_tf32(v.y);
            As[row*36 + c4+2] = to_tf32(v.z);
            As[row*36 + c4+3] = to_tf32(v.w);
        }
#pragma unroll
        for (int r = 0; r < 4; r++) {
            int id = tid + r*256;
            int row = id >> 5, c4 = (id & 31) * 4;
            float4 v = *(const float4*)&W[(size_t)(kc+row)*Ncols + n0 + c4];
            Ws[row*132 + c4+0] = to_tf32(v.x);
            Ws[row*132 + c4+1] = to_tf32(v.y);
            Ws[row*132 + c4+2] = to_tf32(v.z);
            Ws[row*132 + c4+3] = to_tf32(v.w);
        }
        __syncthreads();
#pragma unroll
        for (int k8 = 0; k8 < 4; k8++) {
            const int ka = k8 * 8;
            uint32_t a[2][4];
#pragma unroll
            for (int mt = 0; mt < 2; mt++) {
                int r0 = wm + mt*16 + gID;
                a[mt][0] = __float_as_uint(As[r0*36 + ka + tig]);
                a[mt][1] = __float_as_uint(As[(r0+8)*36 + ka + tig]);
                a[mt][2] = __float_as_uint(As[r0*36 + ka + tig + 4]);
                a[mt][3] = __float_as_uint(As[(r0+8)*36 + ka + tig + 4]);
            }
#pragma unroll
            for (int nt = 0; nt < 8; nt++) {
                int cb = wn + nt*8 + gID;
                uint32_t b0 = __float_as_uint(Ws[(ka+tig)*132 + cb]);
                uint32_t b1 = __float_as_uint(Ws[(ka+tig+4)*132 + cb]);
#pragma unroll
                for (int mt = 0; mt < 2; mt++)
                    mma_tf32(acc[mt][nt], a[mt], b0, b1);
            }
        }
        __syncthreads();
    }

    if (EPI != 2) {
#pragma unroll
        for (int mt = 0; mt < 2; mt++) {
            int row = m0 + wm + mt*16 + gID;
#pragma unroll
            for (int nt = 0; nt < 8; nt++) {
                int col = n0 + wn + nt*8 + 2*tig;
                float b0v = bias ? bias[col]   : 0.f;
                float b1v = bias ? bias[col+1] : 0.f;
                float v0 = acc[mt][nt][0] + b0v;
                float v1 = acc[mt][nt][1] + b1v;
                float v2 = acc[mt][nt][2] + b0v;
                float v3 = acc[mt][nt][3] + b1v;
                if (EPI == 1) {
                    v0 = 0.5f*v0*(1.f + erff(v0*0.70710678118654752f));
                    v1 = 0.5f*v1*(1.f + erff(v1*0.70710678118654752f));
                    v2 = 0.5f*v2*(1.f + erff(v2*0.70710678118654752f));
                    v3 = 0.5f*v3*(1.f + erff(v3*0.70710678118654752f));
                }
                *(float2*)&Cout[(size_t)row*Ncols + col]     = make_float2(v0, v1);
                *(float2*)&Cout[(size_t)(row+8)*Ncols + col] = make_float2(v2, v3);
            }
        }
    } else {
        // residual + LayerNorm epilogue (Ncols == 128, n0 == 0)
        float s1[2][2] = {{0.f,0.f},{0.f,0.f}};
        float s2[2][2] = {{0.f,0.f},{0.f,0.f}};
#pragma unroll
        for (int mt = 0; mt < 2; mt++) {
            int row = m0 + wm + mt*16 + gID;
#pragma unroll
            for (int nt = 0; nt < 8; nt++) {
                int col = wn + nt*8 + 2*tig;
                float b0v = bias[col], b1v = bias[col+1];
                float x0 = acc[mt][nt][0] + b0v + resid[(size_t)row*128 + col];
                float x1 = acc[mt][nt][1] + b1v + resid[(size_t)row*128 + col+1];
                float x2 = acc[mt][nt][2] + b0v + resid[(size_t)(row+8)*128 + col];
                float x3 = acc[mt][nt][3] + b1v + resid[(size_t)(row+8)*128 + col+1];
                acc[mt][nt][0]=x0; acc[mt][nt][1]=x1; acc[mt][nt][2]=x2; acc[mt][nt][3]=x3;
                s1[mt][0] += x0 + x1;       s1[mt][1] += x2 + x3;
                s2[mt][0] += x0*x0 + x1*x1; s2[mt][1] += x2*x2 + x3*x3;
            }
        }
#pragma unroll
        for (int mt = 0; mt < 2; mt++)
#pragma unroll
            for (int h = 0; h < 2; h++) {
                s1[mt][h] += __shfl_xor_sync(0xffffffffu, s1[mt][h], 1);
                s1[mt][h] += __shfl_xor_sync(0xffffffffu, s1[mt][h], 2);
                s2[mt][h] += __shfl_xor_sync(0xffffffffu, s2[mt][h], 1);
                s2[mt][h] += __shfl_xor_sync(0xffffffffu, s2[mt][h], 2);
            }
        if (tig == 0) {
#pragma unroll
            for (int mt = 0; mt < 2; mt++)
#pragma unroll
                for (int h = 0; h < 2; h++) {
                    int lr = wm + mt*16 + gID + h*8;
                    atomicAdd(&rs1[lr], s1[mt][h]);
                    atomicAdd(&rs2[lr], s2[mt][h]);
                }
        }
        __syncthreads();
#pragma unroll
        for (int mt = 0; mt < 2; mt++) {
            int lr = wm + mt*16 + gID;
            float mu0 = rs1[lr]   * (1.f/128.f);
            float mu1 = rs1[lr+8] * (1.f/128.f);
            float rstd0 = rsqrtf(rs2[lr]  *(1.f/128.f) - mu0*mu0 + 1e-5f);
            float rstd1 = rsqrtf(rs2[lr+8]*(1.f/128.f) - mu1*mu1 + 1e-5f);
            int row = m0 + lr;
#pragma unroll
            for (int nt = 0; nt < 8; nt++) {
                int col = wn + nt*8 + 2*tig;
                float g0 = lng[col], g1 = lng[col+1];
                float bb0 = lnb[col], bb1 = lnb[col+1];
                float y0 = (acc[mt][nt][0]-mu0)*rstd0*g0 + bb0;
                float y1 = (acc[mt][nt][1]-mu0)*rstd0*g1 + bb1;
                float y2 = (acc[mt][nt][2]-mu1)*rstd1*g0 + bb0;
                float y3 = (acc[mt][nt][3]-mu1)*rstd1*g1 + bb1;
                *(float2*)&Cout[(size_t)row*128 + col]     = make_float2(y0, y1);
                *(float2*)&Cout[(size_t)(row+8)*128 + col] = make_float2(y2, y3);
            }
        }
    }
}

// ---------------- fused attention block (tf32 mma core) ---------------------
// One block = 16 queries = 128 edges. D=(ai-aj) in SMEM (e-major, tf32),
// 128^3 GEMM on tensor pipe, relu+bias, masked per-channel softmax over K,
// V-gather weighted sum, residual + LayerNorm.
__global__ __launch_bounds__(256) void attn_kernel(
    const float* __restrict__ ai,   const float* __restrict__ asrc,
    const float* __restrict__ V,    const int*   __restrict__ gidx,
    const int*   __restrict__ gcnt, const float* __restrict__ Wat,
    const float* __restrict__ bat,  float* __restrict__ out,
    const float* __restrict__ g1,   const float* __restrict__ b1)
{
    extern __shared__ float sm[];
    float* sD   = sm;                    // [128][132]  D (tf32), then logits
    float* sW   = sm + 128*132;          // [32][132]
    int*   snid = (int*)(sW + 32*132);   // [128]
    int*   scnt = snid + 128;            // [16]

    const int tid = threadIdx.x;
    const int q0  = blockIdx.x * 16;
    const int b   = q0 / NN;

    if (tid < 128) snid[tid] = gidx[(size_t)q0*KNB + tid];
    if (tid < 16)  scnt[tid] = gcnt[q0 + tid];
    __syncthreads();

    // build D (e-major, tf32): sD[e][c] = ai[q][c] - asrc[nid][c]
    {
        int e = tid >> 1, half = tid & 1;
        int q = e >> 3;
        int nid = snid[e];
        const float4* arow = (const float4*)(ai   + ((size_t)(q0+q))*CC + half*64);
        const float4* srow = (const float4*)(asrc + ((size_t)b*LL + nid)*CC + half*64);
#pragma unroll
        for (int i = 0; i < 16; i++) {
            float4 av = arow[i], sv = srow[i];
            int c = half*64 + i*4;
            sD[e*132 + c+0] = to_tf32(av.x - sv.x);
            sD[e*132 + c+1] = to_tf32(av.y - sv.y);
            sD[e*132 + c+2] = to_tf32(av.z - sv.z);
            sD[e*132 + c+3] = to_tf32(av.w - sv.w);
        }
    }

    const int lane = tid & 31, warp = tid >> 5;
    const int wm = (warp & 3) * 32, wn = (warp >> 2) * 64;
    const int gID = lane >> 2, tig = lane & 3;

    float acc[2][8][4];
#pragma unroll
    for (int mt = 0; mt < 2; mt++)
#pragma unroll
        for (int nt = 0; nt < 8; nt++)
#pragma unroll
            for (int c = 0; c < 4; c++) acc[mt][nt][c] = 0.f;

    for (int kc = 0; kc < 128; kc += 32) {
#pragma unroll
        for (int r = 0; r < 4; r++) {
            int id = tid + r*256;
            int row = id >> 5, c4 = (id & 31) * 4;
            float4 v = *(const float4*)&Wat[(size_t)(kc+row)*CC + c4];
            sW[row*132 + c4+0] = to_tf32(v.x);
            sW[row*132 + c4+1] = to_tf32(v.y);
            sW[row*132 + c4+2] = to_tf32(v.z);
            sW[row*132 + c4+3] = to_tf32(v.w);
        }
        __syncthreads();
#pragma unroll
        for (int k8 = 0; k8 < 4; k8++) {
            const int ka = k8 * 8;
            uint32_t a[2][4];
#pragma unroll
            for (int mt = 0; mt < 2; mt++) {
                int r0 = wm + mt*16 + gID;
                a[mt][0] = __float_as_uint(sD[r0*132 + kc + ka + tig]);
                a[mt][1] = __float_as_uint(sD[(r0+8)*132 + kc + ka + tig]);
                a[mt][2] = __float_as_uint(sD[r0*132 + kc + ka + tig + 4]);
                a[mt][3] = __float_as_uint(sD[(r0+8)*132 + kc + ka + tig + 4]);
            }
#pragma unroll
            for (int nt = 0; nt < 8; nt++) {
                int cb = wn + nt*8 + gID;
                uint32_t b0 = __float_as_uint(sW[(ka+tig)*132 + cb]);
                uint32_t b1 = __float_as_uint(sW[(ka+tig+4)*132 + cb]);
#pragma unroll
                for (int mt = 0; mt < 2; mt++)
                    mma_tf32(acc[mt][nt], a[mt], b0, b1);
            }
        }
        __syncthreads();
    }

    // logits = relu(acc + bias) -> sD[e][c]
#pragma unroll
    for (int mt = 0; mt < 2; mt++) {
        int e = wm + mt*16 + gID;
#pragma unroll
        for (int nt = 0; nt < 8; nt++) {
            int c = wn + nt*8 + 2*tig;
            float b0v = bat[c], b1v = bat[c+1];
            sD[e*132 + c]       = fmaxf(acc[mt][nt][0] + b0v, 0.f);
            sD[e*132 + c+1]     = fmaxf(acc[mt][nt][1] + b1v, 0.f);
            sD[(e+8)*132 + c]   = fmaxf(acc[mt][nt][2] + b0v, 0.f);
            sD[(e+8)*132 + c+1] = fmaxf(acc[mt][nt][3] + b1v, 0.f);
        }
    }
    __syncthreads();

    // softmax over valid k per channel + V gather + residual + LN
    {
        const int q  = tid >> 4;
        const int c0 = (tid & 15) * 8;
        const int kcnt = scnt[q];

        float mx[8], sum[8], upd[8];
#pragma unroll
        for (int j = 0; j < 8; j++) { mx[j] = -1e30f; sum[j] = 0.f; upd[j] = 0.f; }

        for (int k = 0; k < kcnt; k++) {
#pragma unroll
            for (int j = 0; j < 8; j++)
                mx[j] = fmaxf(mx[j], sD[(q*8+k)*132 + c0 + j]);
        }
        for (int k = 0; k < kcnt; k++) {
            int nid = snid[q*8 + k];
            const float4* vr = (const float4*)(V + ((size_t)b*LL + nid)*CC + c0);
            float4 v0 = vr[0], v1 = vr[1];
            float vv[8] = {v0.x,v0.y,v0.z,v0.w,v1.x,v1.y,v1.z,v1.w};
#pragma unroll
            for (int j = 0; j < 8; j++) {
                float w = expf(sD[(q*8+k)*132 + c0 + j] - mx[j]);
                sum[j] += w;
                upd[j] = fmaf(w, vv[j], upd[j]);
            }
        }
#pragma unroll
        for (int j = 0; j < 8; j++) upd[j] /= fmaxf(sum[j], 1e-9f);

        float x[8]; float s = 0.f;
        const float* orow = out + (size_t)(q0+q)*CC + c0;
#pragma unroll
        for (int j = 0; j < 8; j++) { x[j] = orow[j] + upd[j]; s += x[j]; }
#pragma unroll
        for (int o = 8; o; o >>= 1) s += __shfl_xor_sync(0xffffffffu, s, o);
        float mu = s * (1.f/128.f);
        float vs = 0.f;
#pragma unroll
        for (int j = 0; j < 8; j++) { float d = x[j]-mu; vs += d*d; }
#pragma unroll
        for (int o = 8; o; o >>= 1) vs += __shfl_xor_sync(0xffffffffu, vs, o);
        float rstd = rsqrtf(vs * (1.f/128.f) + 1e-5f);

        float y[8];
#pragma unroll
        for (int j = 0; j < 8; j++)
            y[j] = (x[j]-mu)*rstd*g1[c0+j] + b1[c0+j];
        float4 s0 = make_float4(y[0],y[1],y[2],y[3]);
        float4 s1 = make_float4(y[4],y[5],y[6],y[7]);
        *(float4*)&out[(size_t)(q0+q)*CC + c0]     = s0;
        *(float4*)&out[(size_t)(q0+q)*CC + c0 + 4] = s1;
    }
}

// ---------------- launch ----------------------------------------------------
extern "C" void kernel_launch(void* const* d_in, const int* in_sizes, int n_in,
                              void* d_out, int out_size)
{
    const float*         q_xyz  = (const float*)d_in[0];
    const float*         q_feat = (const float*)d_in[1];
    const float*         kv_xyz = (const float*)d_in[2];
    const float*         kv_feat= (const float*)d_in[3];
    const unsigned char* kv_pad = (const unsigned char*)d_in[4];
    const float* W_lin  = (const float*)d_in[5];
    const float* b_lin  = (const float*)d_in[6];
    const float* W_src  = (const float*)d_in[7];
    const float* W_dst  = (const float*)d_in[8];
    const float* W_attn = (const float*)d_in[9];
    const float* b_attn = (const float*)d_in[10];
    const float* ln1_g  = (const float*)d_in[11];
    const float* ln1_b  = (const float*)d_in[12];
    const float* W_ff1  = (const float*)d_in[13];
    const float* b_ff1  = (const float*)d_in[14];
    const float* W_ff2  = (const float*)d_in[15];
    const float* b_ff2  = (const float*)d_in[16];
    const float* ln2_g  = (const float*)d_in[17];
    const float* ln2_b  = (const float*)d_in[18];
    float* out = (float*)d_out;

    void *p_idx, *p_cnt, *p_asrc, *p_v, *p_ai, *p_h;
    cudaGetSymbolAddress(&p_idx,  g_idx);
    cudaGetSymbolAddress(&p_cnt,  g_cnt);
    cudaGetSymbolAddress(&p_asrc, g_asrc);
    cudaGetSymbolAddress(&p_v,    g_v);
    cudaGetSymbolAddress(&p_ai,   g_ai);
    cudaGetSymbolAddress(&p_h,    g_h);
    int*   idx_p  = (int*)p_idx;
    int*   cnt_p  = (int*)p_cnt;
    float* asrc_p = (float*)p_asrc;
    float* v_p    = (float*)p_v;
    float* ai_p   = (float*)p_ai;
    float* h_p    = (float*)p_h;

    const int KNN_SMEM  = 3*LL*4 + LL;
    const int ATTN_SMEM = (128*132 + 32*132)*4 + 128*4 + 16*4;
    cudaFuncSetAttribute(knn_kernel,  cudaFuncAttributeMaxDynamicSharedMemorySize, KNN_SMEM);
    cudaFuncSetAttribute(attn_kernel, cudaFuncAttributeMaxDynamicSharedMemorySize, ATTN_SMEM);

    cudaMemcpyAsync(out, q_feat, (size_t)BB*NN*CC*sizeof(float),
                    cudaMemcpyDeviceToDevice, 0);

    knn_kernel<<<dim3(BB, NN/128), 128, KNN_SMEM>>>(q_xyz, kv_xyz, kv_pad, idx_p, cnt_p);

    const int BL = BB*LL;   // 32768
    const int BN = BB*NN;   // 16384

    for (int l = 0; l < 2; l++) {
        const size_t oCC  = (size_t)l * CC * CC;
        const size_t oC   = (size_t)l * CC;
        const size_t oF1  = (size_t)l * CC * FFD;
        const size_t oF   = (size_t)l * FFD;
        const size_t oF2  = (size_t)l * FFD * CC;

        // Asrc = kv_feat @ W_src ; V = kv_feat @ W_lin + b_lin
        gemm_mma<128,0><<<dim3(BL/128,1), 256>>>(
            kv_feat, W_src + oCC, nullptr, asrc_p, CC, nullptr, nullptr, nullptr);
        gemm_mma<128,0><<<dim3(BL/128,1), 256>>>(
            kv_feat, W_lin + oCC, b_lin + oC, v_p, CC, nullptr, nullptr, nullptr);
        // ai = out @ W_dst
        gemm_mma<128,0><<<dim3(BN/128,1), 256>>>(
            out, W_dst + oCC, nullptr, ai_p, CC, nullptr, nullptr, nullptr);
        // fused attention + residual + LN1
        attn_kernel<<<BN/16, 256, ATTN_SMEM>>>(
            ai_p, asrc_p, v_p, idx_p, cnt_p,
            W_attn + oCC, b_attn + oC, out, ln1_g + oC, ln1_b + oC);
        // h = gelu(out @ W_ff1 + b_ff1)
        gemm_mma<128,1><<<dim3(BN/128, FFD/128), 256>>>(
            out, W_ff1 + oF1, b_ff1 + oF, h_p, FFD, nullptr, nullptr, nullptr);
        // out = LN2(out + h @ W_ff2 + b_ff2)
        gemm_mma<512,2><<<dim3(BN/128,1), 256>>>(
            h_p, W_ff2 + oF2, b_ff2 + oC, out, CC, out, ln2_g + oC, ln2_b + oC);
    }
}

// round 3
// speedup vs baseline: 2.1422x; 1.1799x over previous
#include <cuda_runtime.h>
#include <math.h>
#include <stdint.h>

#define BB   8
#define NN   2048
#define LL   4096
#define CC   128
#define KNB  8
#define FFD  512
#define RR2  0.04f

// ---------------- scratch (device globals; no runtime allocation) ----------
__device__ int   g_idx [BB*NN*KNB];
__device__ int   g_cnt [BB*NN];
__device__ float g_S  [(size_t)BB*LL*CC];   // kv_feat @ Wsa
__device__ float g_v  [(size_t)BB*LL*CC];   // kv_feat @ W_lin + b_lin
__device__ float g_P  [(size_t)BB*NN*CC];   // out @ Wda + b_attn
__device__ float g_h  [(size_t)BB*NN*FFD];
__device__ float g_wda[2*CC*CC];
__device__ float g_wsa[2*CC*CC];

__device__ __forceinline__ float to_tf32(float x) {
    float r;
    asm("cvt.rna.tf32.f32 %0, %1;" : "=f"(r) : "f"(x));
    return r;
}

__device__ __forceinline__ void mma_tf32(float* c, const uint32_t* a,
                                         uint32_t b0, uint32_t b1) {
    asm volatile(
        "mma.sync.aligned.m16n8k8.row.col.f32.tf32.tf32.f32 "
        "{%0,%1,%2,%3}, {%4,%5,%6,%7}, {%8,%9}, {%0,%1,%2,%3};"
        : "+f"(c[0]), "+f"(c[1]), "+f"(c[2]), "+f"(c[3])
        : "r"(a[0]), "r"(a[1]), "r"(a[2]), "r"(a[3]), "r"(b0), "r"(b1));
}

// ---------------- kNN radius search ---------------------------------------
__global__ __launch_bounds__(128) void knn_kernel(
    const float* __restrict__ qxyz, const float* __restrict__ kxyz,
    const unsigned char* __restrict__ kpad,
    int* __restrict__ gidx, int* __restrict__ gcnt)
{
    extern __shared__ float sh[];
    float* sx = sh;                               // [3*LL]
    unsigned char* sp = (unsigned char*)(sh + 3*LL);

    const int b = blockIdx.x;
    for (int i = threadIdx.x; i < 3*LL; i += blockDim.x)
        sx[i] = kxyz[(size_t)b*3*LL + i];
    for (int i = threadIdx.x; i < LL; i += blockDim.x)
        sp[i] = kpad[(size_t)b*LL + i];
    __syncthreads();

    const int q = blockIdx.y * blockDim.x + threadIdx.x;
    const float qx = qxyz[((size_t)b*NN + q)*3 + 0];
    const float qy = qxyz[((size_t)b*NN + q)*3 + 1];
    const float qz = qxyz[((size_t)b*NN + q)*3 + 2];

    float bd[KNB]; int bi[KNB];
#pragma unroll
    for (int k = 0; k < KNB; k++) { bd[k] = 1e30f; bi[k] = 0; }

    for (int j = 0; j < LL; j++) {
        float dx = sx[3*j+0] - qx;
        float dy = sx[3*j+1] - qy;
        float dz = sx[3*j+2] - qz;
        float d2 = fmaf(dx, dx, fmaf(dy, dy, dz*dz));
        if (d2 <= RR2 && d2 < bd[KNB-1] && !sp[j]) {
            float v = d2; int vi = j;
#pragma unroll
            for (int k = 0; k < KNB; k++) {
                if (v < bd[k]) {
                    float tf = bd[k]; bd[k] = v; v = tf;
                    int   ti = bi[k]; bi[k] = vi; vi = ti;
                }
            }
        }
    }
    int cnt = 0;
#pragma unroll
    for (int k = 0; k < KNB; k++) cnt += (bd[k] <= RR2) ? 1 : 0;
#pragma unroll
    for (int k = 0; k < KNB; k++)
        gidx[((size_t)b*NN + q)*KNB + k] = bi[k];
    gcnt[b*NN + q] = cnt;
}

// ---------------- weight product prep (exact fp32) --------------------------
// grid (4 col-chunks, 2 row-halves, 4 products); product p: layer=p>>1,
// A = (p&1 ? W_src : W_dst), Out = (p&1 ? Wsa : Wda) = A @ W_attn.
__global__ __launch_bounds__(256) void wprep_kernel(
    const float* __restrict__ Wd, const float* __restrict__ Ws,
    const float* __restrict__ Wa,
    float* __restrict__ Wda, float* __restrict__ Wsa)
{
    __shared__ float sA[64*132];
    const int p = blockIdx.z;
    const int layer = p >> 1;
    const float* A  = ((p & 1) ? Ws : Wd) + (size_t)layer*CC*CC;
    const float* Wm = Wa + (size_t)layer*CC*CC;
    float* O        = ((p & 1) ? Wsa : Wda) + (size_t)layer*CC*CC;

    const int r0 = blockIdx.y * 64;
    const int n0 = blockIdx.x * 32;
    const int tid = threadIdx.x;

    for (int i = tid; i < 64*32; i += 256) {
        int row = i >> 5, c4 = (i & 31) * 4;
        float4 v = *(const float4*)&A[(size_t)(r0+row)*CC + c4];
        sA[row*132 + c4+0] = v.x;
        sA[row*132 + c4+1] = v.y;
        sA[row*132 + c4+2] = v.z;
        sA[row*132 + c4+3] = v.w;
    }
    __syncthreads();

    const int c  = n0 + (tid & 31);
    const int rr = (tid >> 5) * 8;
    float acc[8] = {0.f,0.f,0.f,0.f,0.f,0.f,0.f,0.f};
    for (int kk = 0; kk < 128; kk++) {
        float w = Wm[(size_t)kk*CC + c];
#pragma unroll
        for (int i = 0; i < 8; i++)
            acc[i] = fmaf(sA[(rr+i)*132 + kk], w, acc[i]);
    }
#pragma unroll
    for (int i = 0; i < 8; i++)
        O[(size_t)(r0+rr+i)*CC + c] = acc[i];
}

// ---------------- tf32 tensor-core GEMM -------------------------------------
// C = epi(A[M,KD] @ W[KD,Ncols] + bias). Block tile 128x128, 8 warps (4x2),
// warp tile 32x64 via m16n8k8 tf32 mma.
// EPI: 0 = (+bias), 1 = (+bias, exact GELU), 2 = (+bias, +resid, LayerNorm)
template<int KD, int EPI>
__global__ __launch_bounds__(256) void gemm_mma(
    const float* __restrict__ A, const float* __restrict__ W,
    const float* __restrict__ bias, float* __restrict__ Cout, int Ncols,
    const float* __restrict__ resid,
    const float* __restrict__ lng, const float* __restrict__ lnb)
{
    __shared__ float As[128*36];
    __shared__ float Ws[32*132];
    __shared__ float rs1[128], rs2[128];

    const int m0 = blockIdx.x * 128;
    const int n0 = blockIdx.y * 128;
    const int tid = threadIdx.x;
    const int lane = tid & 31, warp = tid >> 5;
    const int wm = (warp & 3) * 32, wn = (warp >> 2) * 64;
    const int gID = lane >> 2, tig = lane & 3;

    if (EPI == 2 && tid < 128) { rs1[tid] = 0.f; rs2[tid] = 0.f; }

    float acc[2][8][4];
#pragma unroll
    for (int mt = 0; mt < 2; mt++)
#pragma unroll
        for (int nt = 0; nt < 8; nt++)
#pragma unroll
            for (int c = 0; c < 4; c++) acc[mt][nt][c] = 0.f;

    for (int kc = 0; kc < KD; kc += 32) {
#pragma unroll
        for (int r = 0; r < 4; r++) {
            int id = tid + r*256;
            int row = id >> 3, c4 = (id & 7) * 4;
            float4 v = *(const float4*)&A[(size_t)(m0+row)*KD + kc + c4];
            As[row*36 + c4+0] = to_tf32(v.x);
            As[row*36 + c4+1] = to_tf32(v.y);
            As[row*36 + c4+2] = to_tf32(v.z);
            As[row*36 + c4+3] = to_tf32(v.w);
        }
#pragma unroll
        for (int r = 0; r < 4; r++) {
            int id = tid + r*256;
            int row = id >> 5, c4 = (id & 31) * 4;
            float4 v = *(const float4*)&W[(size_t)(kc+row)*Ncols + n0 + c4];
            Ws[row*132 + c4+0] = to_tf32(v.x);
            Ws[row*132 + c4+1] = to_tf32(v.y);
            Ws[row*132 + c4+2] = to_tf32(v.z);
            Ws[row*132 + c4+3] = to_tf32(v.w);
        }
        __syncthreads();
#pragma unroll
        for (int k8 = 0; k8 < 4; k8++) {
            const int ka = k8 * 8;
            uint32_t a[2][4];
#pragma unroll
            for (int mt = 0; mt < 2; mt++) {
                int r0 = wm + mt*16 + gID;
                a[mt][0] = __float_as_uint(As[r0*36 + ka + tig]);
                a[mt][1] = __float_as_uint(As[(r0+8)*36 + ka + tig]);
                a[mt][2] = __float_as_uint(As[r0*36 + ka + tig + 4]);
                a[mt][3] = __float_as_uint(As[(r0+8)*36 + ka + tig + 4]);
            }
#pragma unroll
            for (int nt = 0; nt < 8; nt++) {
                int cb = wn + nt*8 + gID;
                uint32_t b0 = __float_as_uint(Ws[(ka+tig)*132 + cb]);
                uint32_t b1 = __float_as_uint(Ws[(ka+tig+4)*132 + cb]);
#pragma unroll
                for (int mt = 0; mt < 2; mt++)
                    mma_tf32(acc[mt][nt], a[mt], b0, b1);
            }
        }
        __syncthreads();
    }

    if (EPI != 2) {
#pragma unroll
        for (int mt = 0; mt < 2; mt++) {
            int row = m0 + wm + mt*16 + gID;
#pragma unroll
            for (int nt = 0; nt < 8; nt++) {
                int col = n0 + wn + nt*8 + 2*tig;
                float b0v = bias ? bias[col]   : 0.f;
                float b1v = bias ? bias[col+1] : 0.f;
                float v0 = acc[mt][nt][0] + b0v;
                float v1 = acc[mt][nt][1] + b1v;
                float v2 = acc[mt][nt][2] + b0v;
                float v3 = acc[mt][nt][3] + b1v;
                if (EPI == 1) {
                    v0 = 0.5f*v0*(1.f + erff(v0*0.70710678118654752f));
                    v1 = 0.5f*v1*(1.f + erff(v1*0.70710678118654752f));
                    v2 = 0.5f*v2*(1.f + erff(v2*0.70710678118654752f));
                    v3 = 0.5f*v3*(1.f + erff(v3*0.70710678118654752f));
                }
                *(float2*)&Cout[(size_t)row*Ncols + col]     = make_float2(v0, v1);
                *(float2*)&Cout[(size_t)(row+8)*Ncols + col] = make_float2(v2, v3);
            }
        }
    } else {
        // residual + LayerNorm epilogue (Ncols == 128, n0 == 0)
        float s1[2][2] = {{0.f,0.f},{0.f,0.f}};
        float s2[2][2] = {{0.f,0.f},{0.f,0.f}};
#pragma unroll
        for (int mt = 0; mt < 2; mt++) {
            int row = m0 + wm + mt*16 + gID;
#pragma unroll
            for (int nt = 0; nt < 8; nt++) {
                int col = wn + nt*8 + 2*tig;
                float b0v = bias[col], b1v = bias[col+1];
                float x0 = acc[mt][nt][0] + b0v + resid[(size_t)row*128 + col];
                float x1 = acc[mt][nt][1] + b1v + resid[(size_t)row*128 + col+1];
                float x2 = acc[mt][nt][2] + b0v + resid[(size_t)(row+8)*128 + col];
                float x3 = acc[mt][nt][3] + b1v + resid[(size_t)(row+8)*128 + col+1];
                acc[mt][nt][0]=x0; acc[mt][nt][1]=x1; acc[mt][nt][2]=x2; acc[mt][nt][3]=x3;
                s1[mt][0] += x0 + x1;       s1[mt][1] += x2 + x3;
                s2[mt][0] += x0*x0 + x1*x1; s2[mt][1] += x2*x2 + x3*x3;
            }
        }
#pragma unroll
        for (int mt = 0; mt < 2; mt++)
#pragma unroll
            for (int h = 0; h < 2; h++) {
                s1[mt][h] += __shfl_xor_sync(0xffffffffu, s1[mt][h], 1);
                s1[mt][h] += __shfl_xor_sync(0xffffffffu, s1[mt][h], 2);
                s2[mt][h] += __shfl_xor_sync(0xffffffffu, s2[mt][h], 1);
                s2[mt][h] += __shfl_xor_sync(0xffffffffu, s2[mt][h], 2);
            }
        if (tig == 0) {
#pragma unroll
            for (int mt = 0; mt < 2; mt++)
#pragma unroll
                for (int h = 0; h < 2; h++) {
                    int lr = wm + mt*16 + gID + h*8;
                    atomicAdd(&rs1[lr], s1[mt][h]);
                    atomicAdd(&rs2[lr], s2[mt][h]);
                }
        }
        __syncthreads();
#pragma unroll
        for (int mt = 0; mt < 2; mt++) {
            int lr = wm + mt*16 + gID;
            float mu0 = rs1[lr]   * (1.f/128.f);
            float mu1 = rs1[lr+8] * (1.f/128.f);
            float rstd0 = rsqrtf(rs2[lr]  *(1.f/128.f) - mu0*mu0 + 1e-5f);
            float rstd1 = rsqrtf(rs2[lr+8]*(1.f/128.f) - mu1*mu1 + 1e-5f);
            int row = m0 + lr;
#pragma unroll
            for (int nt = 0; nt < 8; nt++) {
                int col = wn + nt*8 + 2*tig;
                float g0 = lng[col], g1 = lng[col+1];
                float bb0 = lnb[col], bb1 = lnb[col+1];
                float y0 = (acc[mt][nt][0]-mu0)*rstd0*g0 + bb0;
                float y1 = (acc[mt][nt][1]-mu0)*rstd0*g1 + bb1;
                float y2 = (acc[mt][nt][2]-mu1)*rstd1*g0 + bb0;
                float y3 = (acc[mt][nt][3]-mu1)*rstd1*g1 + bb1;
                *(float2*)&Cout[(size_t)row*128 + col]     = make_float2(y0, y1);
                *(float2*)&Cout[(size_t)(row+8)*128 + col] = make_float2(y2, y3);
            }
        }
    }
}

// ---------------- light attention: gather + softmax + residual + LN ---------
// one warp per query; lane owns 4 channels. logits[k][c] = relu(P[q]-S[nid]),
// per-channel softmax over valid k, weighted V sum, residual + LayerNorm.
__global__ __launch_bounds__(256) void attn2_kernel(
    const float* __restrict__ P, const float* __restrict__ S,
    const float* __restrict__ V, const int* __restrict__ gidx,
    const int* __restrict__ gcnt,
    const float* __restrict__ resid, float* __restrict__ out,
    const float* __restrict__ g1, const float* __restrict__ b1)
{
    const int warp = threadIdx.x >> 5, lane = threadIdx.x & 31;
    const int q = blockIdx.x * 8 + warp;       // global over B*N
    const int b = q / NN;
    const int c0 = lane * 4;

    const float4 p4 = *(const float4*)&P[(size_t)q*CC + c0];
    const int kcnt = gcnt[q];
    int nid[KNB];
#pragma unroll
    for (int k = 0; k < KNB; k++) nid[k] = gidx[(size_t)q*KNB + k];

    float4 lg[KNB];
    float mx0 = -1e30f, mx1 = -1e30f, mx2 = -1e30f, mx3 = -1e30f;
#pragma unroll
    for (int k = 0; k < KNB; k++) {
        if (k < kcnt) {
            const float4 s4 = *(const float4*)&S[((size_t)b*LL + nid[k])*CC + c0];
            float4 l;
            l.x = fmaxf(p4.x - s4.x, 0.f);
            l.y = fmaxf(p4.y - s4.y, 0.f);
            l.z = fmaxf(p4.z - s4.z, 0.f);
            l.w = fmaxf(p4.w - s4.w, 0.f);
            lg[k] = l;
            mx0 = fmaxf(mx0, l.x); mx1 = fmaxf(mx1, l.y);
            mx2 = fmaxf(mx2, l.z); mx3 = fmaxf(mx3, l.w);
        }
    }

    float su0=0.f, su1=0.f, su2=0.f, su3=0.f;
    float up0=0.f, up1=0.f, up2=0.f, up3=0.f;
#pragma unroll
    for (int k = 0; k < KNB; k++) {
        if (k < kcnt) {
            const float4 v4 = *(const float4*)&V[((size_t)b*LL + nid[k])*CC + c0];
            float w0 = expf(lg[k].x - mx0);
            float w1 = expf(lg[k].y - mx1);
            float w2 = expf(lg[k].z - mx2);
            float w3 = expf(lg[k].w - mx3);
            su0 += w0; su1 += w1; su2 += w2; su3 += w3;
            up0 = fmaf(w0, v4.x, up0);
            up1 = fmaf(w1, v4.y, up1);
            up2 = fmaf(w2, v4.z, up2);
            up3 = fmaf(w3, v4.w, up3);
        }
    }
    up0 /= fmaxf(su0, 1e-9f);
    up1 /= fmaxf(su1, 1e-9f);
    up2 /= fmaxf(su2, 1e-9f);
    up3 /= fmaxf(su3, 1e-9f);

    const float4 r4 = *(const float4*)&resid[(size_t)q*CC + c0];
    float x0 = r4.x + up0, x1 = r4.y + up1, x2 = r4.z + up2, x3 = r4.w + up3;

    float s = x0 + x1 + x2 + x3;
#pragma unroll
    for (int o = 16; o; o >>= 1) s += __shfl_xor_sync(0xffffffffu, s, o);
    float mu = s * (1.f/128.f);
    float d0 = x0-mu, d1 = x1-mu, d2 = x2-mu, d3 = x3-mu;
    float vs = d0*d0 + d1*d1 + d2*d2 + d3*d3;
#pragma unroll
    for (int o = 16; o; o >>= 1) vs += __shfl_xor_sync(0xffffffffu, vs, o);
    float rstd = rsqrtf(vs * (1.f/128.f) + 1e-5f);

    const float4 gg = *(const float4*)&g1[c0];
    const float4 bb = *(const float4*)&b1[c0];
    float4 y;
    y.x = d0*rstd*gg.x + bb.x;
    y.y = d1*rstd*gg.y + bb.y;
    y.z = d2*rstd*gg.z + bb.z;
    y.w = d3*rstd*gg.w + bb.w;
    *(float4*)&out[(size_t)q*CC + c0] = y;
}

// ---------------- launch ----------------------------------------------------
extern "C" void kernel_launch(void* const* d_in, const int* in_sizes, int n_in,
                              void* d_out, int out_size)
{
    const float*         q_xyz  = (const float*)d_in[0];
    const float*         q_feat = (const float*)d_in[1];
    const float*         kv_xyz = (const float*)d_in[2];
    const float*         kv_feat= (const float*)d_in[3];
    const unsigned char* kv_pad = (const unsigned char*)d_in[4];
    const float* W_lin  = (const float*)d_in[5];
    const float* b_lin  = (const float*)d_in[6];
    const float* W_src  = (const float*)d_in[7];
    const float* W_dst  = (const float*)d_in[8];
    const float* W_attn = (const float*)d_in[9];
    const float* b_attn = (const float*)d_in[10];
    const float* ln1_g  = (const float*)d_in[11];
    const float* ln1_b  = (const float*)d_in[12];
    const float* W_ff1  = (const float*)d_in[13];
    const float* b_ff1  = (const float*)d_in[14];
    const float* W_ff2  = (const float*)d_in[15];
    const float* b_ff2  = (const float*)d_in[16];
    const float* ln2_g  = (const float*)d_in[17];
    const float* ln2_b  = (const float*)d_in[18];
    float* out = (float*)d_out;

    void *p_idx, *p_cnt, *p_S, *p_v, *p_P, *p_h, *p_wda, *p_wsa;
    cudaGetSymbolAddress(&p_idx, g_idx);
    cudaGetSymbolAddress(&p_cnt, g_cnt);
    cudaGetSymbolAddress(&p_S,   g_S);
    cudaGetSymbolAddress(&p_v,   g_v);
    cudaGetSymbolAddress(&p_P,   g_P);
    cudaGetSymbolAddress(&p_h,   g_h);
    cudaGetSymbolAddress(&p_wda, g_wda);
    cudaGetSymbolAddress(&p_wsa, g_wsa);
    int*   idx_p = (int*)p_idx;
    int*   cnt_p = (int*)p_cnt;
    float* S_p   = (float*)p_S;
    float* v_p   = (float*)p_v;
    float* P_p   = (float*)p_P;
    float* h_p   = (float*)p_h;
    float* wda_p = (float*)p_wda;
    float* wsa_p = (float*)p_wsa;

    const int KNN_SMEM = 3*LL*4 + LL;
    cudaFuncSetAttribute(knn_kernel, cudaFuncAttributeMaxDynamicSharedMemorySize, KNN_SMEM);

    knn_kernel<<<dim3(BB, NN/128), 128, KNN_SMEM>>>(q_xyz, kv_xyz, kv_pad, idx_p, cnt_p);
    wprep_kernel<<<dim3(4, 2, 4), 256>>>(W_dst, W_src, W_attn, wda_p, wsa_p);

    const int BL = BB*LL;   // 32768
    const int BN = BB*NN;   // 16384

    for (int l = 0; l < 2; l++) {
        const size_t oCC = (size_t)l * CC * CC;
        const size_t oC  = (size_t)l * CC;
        const size_t oF1 = (size_t)l * CC * FFD;
        const size_t oF  = (size_t)l * FFD;
        const size_t oF2 = (size_t)l * FFD * CC;
        const float* in_l = (l == 0) ? q_feat : out;

        // S = kv_feat @ Wsa ; V = kv_feat @ W_lin + b_lin
        gemm_mma<128,0><<<dim3(BL/128,1), 256>>>(
            kv_feat, wsa_p + oCC, nullptr, S_p, CC, nullptr, nullptr, nullptr);
        gemm_mma<128,0><<<dim3(BL/128,1), 256>>>(
            kv_feat, W_lin + oCC, b_lin + oC, v_p, CC, nullptr, nullptr, nullptr);
        // P = in_l @ Wda + b_attn
        gemm_mma<128,0><<<dim3(BN/128,1), 256>>>(
            in_l, wda_p + oCC, b_attn + oC, P_p, CC, nullptr, nullptr, nullptr);
        // attention gather/softmax + residual + LN1
        attn2_kernel<<<BN/8, 256>>>(
            P_p, S_p, v_p, idx_p, cnt_p, in_l, out, ln1_g + oC, ln1_b + oC);
        // h = gelu(out @ W_ff1 + b_ff1)
        gemm_mma<128,1><<<dim3(BN/128, FFD/128), 256>>>(
            out, W_ff1 + oF1, b_ff1 + oF, h_p, FFD, nullptr, nullptr, nullptr);
        // out = LN2(out + h @ W_ff2 + b_ff2)
        gemm_mma<512,2><<<dim3(BN/128,1), 256>>>(
            h_p, W_ff2 + oF2, b_ff2 + oC, out, CC, out, ln2_g + oC, ln2_b + oC);
    }
}

// round 4
// speedup vs baseline: 2.4561x; 1.1465x over previous
#include <cuda_runtime.h>
#include <math.h>
#include <stdint.h>

#define BB   8
#define NN   2048
#define LL   4096
#define CC   128
#define KNB  8
#define FFD  512
#define RR2  0.04f

// ---------------- scratch (device globals; no runtime allocation) ----------
__device__ int   g_idx [BB*NN*KNB];
__device__ int   g_cnt [BB*NN];
__device__ float g_SV [(size_t)BB*LL*512];  // [S0|V0|S1|V1] per kv row
__device__ float g_P  [(size_t)BB*NN*CC];
__device__ float g_h  [(size_t)BB*NN*FFD];
__device__ float g_wda[2*CC*CC];
__device__ float g_wsv[CC*512];             // [Wsa0|Wlin0|Wsa1|Wlin1]
__device__ float g_bsv[512];

__device__ __forceinline__ float to_tf32(float x) {
    float r;
    asm("cvt.rna.tf32.f32 %0, %1;" : "=f"(r) : "f"(x));
    return r;
}

__device__ __forceinline__ void mma_tf32(float* c, const uint32_t* a,
                                         uint32_t b0, uint32_t b1) {
    asm volatile(
        "mma.sync.aligned.m16n8k8.row.col.f32.tf32.tf32.f32 "
        "{%0,%1,%2,%3}, {%4,%5,%6,%7}, {%8,%9}, {%0,%1,%2,%3};"
        : "+f"(c[0]), "+f"(c[1]), "+f"(c[2]), "+f"(c[3])
        : "r"(a[0]), "r"(a[1]), "r"(a[2]), "r"(a[3]), "r"(b0), "r"(b1));
}

__device__ __forceinline__ void cp16(float* dst, const float* src) {
    uint32_t d = (uint32_t)__cvta_generic_to_shared(dst);
    asm volatile("cp.async.ca.shared.global [%0], [%1], 16;" :: "r"(d), "l"(src));
}

// ---------------- kNN radius search (4-way L split) -------------------------
// block: 512 threads = 128 queries x 4 partitions; grid (B, N/128).
__global__ __launch_bounds__(512) void knn_kernel(
    const float* __restrict__ qxyz, const float* __restrict__ kxyz,
    const unsigned char* __restrict__ kpad,
    int* __restrict__ gidx, int* __restrict__ gcnt)
{
    extern __shared__ float sh[];
    float* sx = sh;                                  // [3*LL]
    unsigned char* sp = (unsigned char*)(sh + 3*LL); // [LL]
    float* md = (float*)(sp + LL);                   // [512*8]
    int*   mi = (int*)(md + 512*8);                  // [512*8]

    const int tid = threadIdx.x;
    const int b = blockIdx.x;
    for (int i = tid; i < 3*LL; i += 512)
        sx[i] = kxyz[(size_t)b*3*LL + i];
    for (int i = tid; i < LL; i += 512)
        sp[i] = kpad[(size_t)b*LL + i];
    __syncthreads();

    const int qi   = tid & 127;
    const int part = tid >> 7;
    const int q = blockIdx.y * 128 + qi;
    const float qx = qxyz[((size_t)b*NN + q)*3 + 0];
    const float qy = qxyz[((size_t)b*NN + q)*3 + 1];
    const float qz = qxyz[((size_t)b*NN + q)*3 + 2];

    float bd[KNB]; int bi[KNB];
#pragma unroll
    for (int k = 0; k < KNB; k++) { bd[k] = 1e30f; bi[k] = 0; }

    const int j0 = part * (LL/4), j1 = j0 + LL/4;
    for (int j = j0; j < j1; j++) {
        float dx = sx[3*j+0] - qx;
        float dy = sx[3*j+1] - qy;
        float dz = sx[3*j+2] - qz;
        float d2 = fmaf(dx, dx, fmaf(dy, dy, dz*dz));
        if (d2 <= RR2 && d2 < bd[KNB-1] && !sp[j]) {
            float v = d2; int vi = j;
#pragma unroll
            for (int k = 0; k < KNB; k++) {
                if (v < bd[k]) {
                    float tf = bd[k]; bd[k] = v; v = tf;
                    int   ti = bi[k]; bi[k] = vi; vi = ti;
                }
            }
        }
    }
#pragma unroll
    for (int k = 0; k < KNB; k++) {
        md[(qi*4 + part)*8 + k] = bd[k];
        mi[(qi*4 + part)*8 + k] = bi[k];
    }
    __syncthreads();

    if (part == 0) {
        float fb[KNB]; int fi[KNB];
#pragma unroll
        for (int k = 0; k < KNB; k++) { fb[k] = 1e30f; fi[k] = 0; }
        for (int p = 0; p < 4; p++) {
            for (int k = 0; k < KNB; k++) {
                float v = md[(qi*4 + p)*8 + k];
                if (v >= fb[KNB-1]) break;   // lists sorted ascending
                int vi = mi[(qi*4 + p)*8 + k];
#pragma unroll
                for (int t = 0; t < KNB; t++) {
                    if (v < fb[t]) {
                        float tf = fb[t]; fb[t] = v; v = tf;
                        int   ti = fi[t]; fi[t] = vi; vi = ti;
                    }
                }
            }
        }
        int cnt = 0;
#pragma unroll
        for (int k = 0; k < KNB; k++) cnt += (fb[k] <= RR2) ? 1 : 0;
#pragma unroll
        for (int k = 0; k < KNB; k++)
            gidx[((size_t)b*NN + q)*KNB + k] = fi[k];
        gcnt[b*NN + q] = cnt;
    }
}

// ---------------- weight product prep (exact fp32) --------------------------
// p: layer=p>>1; p&1==0 -> Wda[layer] = W_dst@W_attn (ld 128)
//                p&1==1 -> Wsa[layer] = W_src@W_attn -> g_wsv cols 256*layer (ld 512)
__global__ __launch_bounds__(256) void wprep_kernel(
    const float* __restrict__ Wd, const float* __restrict__ Ws,
    const float* __restrict__ Wa,
    float* __restrict__ Wda, float* __restrict__ Wsv)
{
    __shared__ float sA[64*132];
    const int p = blockIdx.z;
    const int layer = p >> 1;
    const float* A  = ((p & 1) ? Ws : Wd) + (size_t)layer*CC*CC;
    const float* Wm = Wa + (size_t)layer*CC*CC;
    float* O;
    int ldo;
    if (p & 1) { O = Wsv + 256*layer; ldo = 512; }
    else       { O = Wda + (size_t)layer*CC*CC; ldo = 128; }

    const int r0 = blockIdx.y * 64;
    const int n0 = blockIdx.x * 32;
    const int tid = threadIdx.x;

    for (int i = tid; i < 64*32; i += 256) {
        int row = i >> 5, c4 = (i & 31) * 4;
        float4 v = *(const float4*)&A[(size_t)(r0+row)*CC + c4];
        sA[row*132 + c4+0] = v.x;
        sA[row*132 + c4+1] = v.y;
        sA[row*132 + c4+2] = v.z;
        sA[row*132 + c4+3] = v.w;
    }
    __syncthreads();

    const int c  = n0 + (tid & 31);
    const int rr = (tid >> 5) * 8;
    float acc[8] = {0.f,0.f,0.f,0.f,0.f,0.f,0.f,0.f};
    for (int kk = 0; kk < 128; kk++) {
        float w = Wm[(size_t)kk*CC + c];
#pragma unroll
        for (int i = 0; i < 8; i++)
            acc[i] = fmaf(sA[(rr+i)*132 + kk], w, acc[i]);
    }
#pragma unroll
    for (int i = 0; i < 8; i++)
        O[(size_t)(r0+rr+i)*ldo + c] = acc[i];
}

// ---------------- copy W_lin into combined WSV + build bias -----------------
__global__ __launch_bounds__(256) void copyk_kernel(
    const float* __restrict__ Wlin, const float* __restrict__ blin,
    float* __restrict__ Wsv, float* __restrict__ bsv)
{
    const int l = blockIdx.y;
    for (int i = blockIdx.x*256 + threadIdx.x; i < CC*CC; i += gridDim.x*256) {
        int row = i >> 7, c = i & 127;
        Wsv[(size_t)row*512 + 256*l + 128 + c] = Wlin[(size_t)l*CC*CC + i];
    }
    if (blockIdx.x == 0) {
        for (int i = threadIdx.x; i < 128; i += 256) {
            bsv[256*l + i]       = 0.f;
            bsv[256*l + 128 + i] = blin[l*CC + i];
        }
    }
}

// ---------------- tf32 tensor-core GEMM, cp.async double-buffered -----------
// C = epi(A[M,KD] @ W[KD,Ncols] + bias). Block tile MTx128, 8 warps (4x2),
// warp tile (MT/4)x64. Two-stage cp.async pipeline, one sync per K-chunk.
// EPI: 0 = (+bias), 1 = (+bias, exact GELU), 2 = (+bias, +resid, LayerNorm)
template<int KD, int MT, int EPI>
__global__ __launch_bounds__(256, 2) void gemm_mma(
    const float* __restrict__ A, const float* __restrict__ W,
    const float* __restrict__ bias, float* __restrict__ Cout, int Ncols,
    const float* __restrict__ resid,
    const float* __restrict__ lng, const float* __restrict__ lnb)
{
    constexpr int MTC = MT / 64;          // m-frag count per warp (1 or 2)
    constexpr int ASZ = MT * 36;
    constexpr int WSZ = 32 * 132;
    extern __shared__ float dynsm[];
    float* Abuf[2] = { dynsm,            dynsm + ASZ + WSZ };
    float* Wbuf[2] = { dynsm + ASZ,      dynsm + 2*ASZ + WSZ };
    __shared__ float rs1[128], rs2[128];

    const int m0 = blockIdx.x * MT;
    const int n0 = blockIdx.y * 128;
    const int tid = threadIdx.x;
    const int lane = tid & 31, warp = tid >> 5;
    const int wm = (warp & 3) * (MT/4), wn = (warp >> 2) * 64;
    const int gID = lane >> 2, tig = lane & 3;

    if (EPI == 2 && tid < MT) { rs1[tid] = 0.f; rs2[tid] = 0.f; }

    float acc[MTC][8][4];
#pragma unroll
    for (int mt = 0; mt < MTC; mt++)
#pragma unroll
        for (int nt = 0; nt < 8; nt++)
#pragma unroll
            for (int c = 0; c < 4; c++) acc[mt][nt][c] = 0.f;

    // stage issue: A chunk MT x 32, W chunk 32 x 128
    auto issue = [&](int st, int kc) {
#pragma unroll
        for (int r = 0; r < MT/32; r++) {          // MT*8 float4 / 256 thr
            int id = tid + r*256;
            int row = id >> 3, c4 = (id & 7) * 4;
            cp16(&Abuf[st][row*36 + c4], &A[(size_t)(m0+row)*KD + kc + c4]);
        }
#pragma unroll
        for (int r = 0; r < 4; r++) {
            int id = tid + r*256;
            int row = id >> 5, c4 = (id & 31) * 4;
            cp16(&Wbuf[st][row*132 + c4], &W[(size_t)(kc+row)*Ncols + n0 + c4]);
        }
    };

    constexpr int NIT = KD / 32;
    issue(0, 0);
    asm volatile("cp.async.commit_group;");

    for (int it = 0; it < NIT; ++it) {
        if (it + 1 < NIT) {
            issue((it+1) & 1, (it+1)*32);
            asm volatile("cp.async.commit_group;");
            asm volatile("cp.async.wait_group 1;");
        } else {
            asm volatile("cp.async.wait_group 0;");
        }
        __syncthreads();
        const float* Ac = Abuf[it & 1];
        const float* Wc = Wbuf[it & 1];
#pragma unroll
        for (int k8 = 0; k8 < 4; k8++) {
            const int ka = k8 * 8;
            uint32_t a[MTC][4];
#pragma unroll
            for (int mt = 0; mt < MTC; mt++) {
                int r0 = wm + mt*16 + gID;
                a[mt][0] = __float_as_uint(to_tf32(Ac[r0*36 + ka + tig]));
                a[mt][1] = __float_as_uint(to_tf32(Ac[(r0+8)*36 + ka + tig]));
                a[mt][2] = __float_as_uint(to_tf32(Ac[r0*36 + ka + tig + 4]));
                a[mt][3] = __float_as_uint(to_tf32(Ac[(r0+8)*36 + ka + tig + 4]));
            }
#pragma unroll
            for (int nt = 0; nt < 8; nt++) {
                int cb = wn + nt*8 + gID;
                uint32_t b0 = __float_as_uint(to_tf32(Wc[(ka+tig)*132 + cb]));
                uint32_t b1 = __float_as_uint(to_tf32(Wc[(ka+tig+4)*132 + cb]));
#pragma unroll
                for (int mt = 0; mt < MTC; mt++)
                    mma_tf32(acc[mt][nt], a[mt], b0, b1);
            }
        }
        __syncthreads();
    }

    if (EPI != 2) {
#pragma unroll
        for (int mt = 0; mt < MTC; mt++) {
            int row = m0 + wm + mt*16 + gID;
#pragma unroll
            for (int nt = 0; nt < 8; nt++) {
                int col = n0 + wn + nt*8 + 2*tig;
                float b0v = bias ? bias[col]   : 0.f;
                float b1v = bias ? bias[col+1] : 0.f;
                float v0 = acc[mt][nt][0] + b0v;
                float v1 = acc[mt][nt][1] + b1v;
                float v2 = acc[mt][nt][2] + b0v;
                float v3 = acc[mt][nt][3] + b1v;
                if (EPI == 1) {
                    v0 = 0.5f*v0*(1.f + erff(v0*0.70710678118654752f));
                    v1 = 0.5f*v1*(1.f + erff(v1*0.70710678118654752f));
                    v2 = 0.5f*v2*(1.f + erff(v2*0.70710678118654752f));
                    v3 = 0.5f*v3*(1.f + erff(v3*0.70710678118654752f));
                }
                *(float2*)&Cout[(size_t)row*Ncols + col]     = make_float2(v0, v1);
                *(float2*)&Cout[(size_t)(row+8)*Ncols + col] = make_float2(v2, v3);
            }
        }
    } else {
        // residual + LayerNorm epilogue (Ncols == 128, n0 == 0)
        float s1[MTC][2], s2[MTC][2];
#pragma unroll
        for (int mt = 0; mt < MTC; mt++) {
            s1[mt][0]=s1[mt][1]=s2[mt][0]=s2[mt][1]=0.f;
            int row = m0 + wm + mt*16 + gID;
#pragma unroll
            for (int nt = 0; nt < 8; nt++) {
                int col = wn + nt*8 + 2*tig;
                float b0v = bias[col], b1v = bias[col+1];
                float x0 = acc[mt][nt][0] + b0v + resid[(size_t)row*128 + col];
                float x1 = acc[mt][nt][1] + b1v + resid[(size_t)row*128 + col+1];
                float x2 = acc[mt][nt][2] + b0v + resid[(size_t)(row+8)*128 + col];
                float x3 = acc[mt][nt][3] + b1v + resid[(size_t)(row+8)*128 + col+1];
                acc[mt][nt][0]=x0; acc[mt][nt][1]=x1; acc[mt][nt][2]=x2; acc[mt][nt][3]=x3;
                s1[mt][0] += x0 + x1;       s1[mt][1] += x2 + x3;
                s2[mt][0] += x0*x0 + x1*x1; s2[mt][1] += x2*x2 + x3*x3;
            }
        }
#pragma unroll
        for (int mt = 0; mt < MTC; mt++)
#pragma unroll
            for (int h = 0; h < 2; h++) {
                s1[mt][h] += __shfl_xor_sync(0xffffffffu, s1[mt][h], 1);
                s1[mt][h] += __shfl_xor_sync(0xffffffffu, s1[mt][h], 2);
                s2[mt][h] += __shfl_xor_sync(0xffffffffu, s2[mt][h], 1);
                s2[mt][h] += __shfl_xor_sync(0xffffffffu, s2[mt][h], 2);
            }
        if (tig == 0) {
#pragma unroll
            for (int mt = 0; mt < MTC; mt++)
#pragma unroll
                for (int h = 0; h < 2; h++) {
                    int lr = wm + mt*16 + gID + h*8;
                    atomicAdd(&rs1[lr], s1[mt][h]);
                    atomicAdd(&rs2[lr], s2[mt][h]);
                }
        }
        __syncthreads();
#pragma unroll
        for (int mt = 0; mt < MTC; mt++) {
            int lr = wm + mt*16 + gID;
            float mu0 = rs1[lr]   * (1.f/128.f);
            float mu1 = rs1[lr+8] * (1.f/128.f);
            float rstd0 = rsqrtf(rs2[lr]  *(1.f/128.f) - mu0*mu0 + 1e-5f);
            float rstd1 = rsqrtf(rs2[lr+8]*(1.f/128.f) - mu1*mu1 + 1e-5f);
            int row = m0 + lr;
#pragma unroll
            for (int nt = 0; nt < 8; nt++) {
                int col = wn + nt*8 + 2*tig;
                float g0 = lng[col], g1 = lng[col+1];
                float bb0 = lnb[col], bb1 = lnb[col+1];
                float y0 = (acc[mt][nt][0]-mu0)*rstd0*g0 + bb0;
                float y1 = (acc[mt][nt][1]-mu0)*rstd0*g1 + bb1;
                float y2 = (acc[mt][nt][2]-mu1)*rstd1*g0 + bb0;
                float y3 = (acc[mt][nt][3]-mu1)*rstd1*g1 + bb1;
                *(float2*)&Cout[(size_t)row*128 + col]     = make_float2(y0, y1);
                *(float2*)&Cout[(size_t)(row+8)*128 + col] = make_float2(y2, y3);
            }
        }
    }
}

// ---------------- light attention: gather + softmax + residual + LN ---------
// one warp per query; lane owns 4 channels. S/V live in g_SV (row stride 512).
__global__ __launch_bounds__(256) void attn2_kernel(
    const float* __restrict__ P, const float* __restrict__ S,
    const float* __restrict__ V, const int* __restrict__ gidx,
    const int* __restrict__ gcnt,
    const float* __restrict__ resid, float* __restrict__ out,
    const float* __restrict__ g1, const float* __restrict__ b1)
{
    const int warp = threadIdx.x >> 5, lane = threadIdx.x & 31;
    const int q = blockIdx.x * 8 + warp;       // global over B*N
    const int b = q / NN;
    const int c0 = lane * 4;

    const float4 p4 = *(const float4*)&P[(size_t)q*CC + c0];
    const int kcnt = gcnt[q];
    int nid[KNB];
#pragma unroll
    for (int k = 0; k < KNB; k++) nid[k] = gidx[(size_t)q*KNB + k];

    float4 lg[KNB];
    float mx0 = -1e30f, mx1 = -1e30f, mx2 = -1e30f, mx3 = -1e30f;
#pragma unroll
    for (int k = 0; k < KNB; k++) {
        if (k < kcnt) {
            const float4 s4 = *(const float4*)&S[((size_t)b*LL + nid[k])*512 + c0];
            float4 l;
            l.x = fmaxf(p4.x - s4.x, 0.f);
            l.y = fmaxf(p4.y - s4.y, 0.f);
            l.z = fmaxf(p4.z - s4.z, 0.f);
            l.w = fmaxf(p4.w - s4.w, 0.f);
            lg[k] = l;
            mx0 = fmaxf(mx0, l.x); mx1 = fmaxf(mx1, l.y);
            mx2 = fmaxf(mx2, l.z); mx3 = fmaxf(mx3, l.w);
        }
    }

    float su0=0.f, su1=0.f, su2=0.f, su3=0.f;
    float up0=0.f, up1=0.f, up2=0.f, up3=0.f;
#pragma unroll
    for (int k = 0; k < KNB; k++) {
        if (k < kcnt) {
            const float4 v4 = *(const float4*)&V[((size_t)b*LL + nid[k])*512 + c0];
            float w0 = expf(lg[k].x - mx0);
            float w1 = expf(lg[k].y - mx1);
            float w2 = expf(lg[k].z - mx2);
            float w3 = expf(lg[k].w - mx3);
            su0 += w0; su1 += w1; su2 += w2; su3 += w3;
            up0 = fmaf(w0, v4.x, up0);
            up1 = fmaf(w1, v4.y, up1);
            up2 = fmaf(w2, v4.z, up2);
            up3 = fmaf(w3, v4.w, up3);
        }
    }
    up0 /= fmaxf(su0, 1e-9f);
    up1 /= fmaxf(su1, 1e-9f);
    up2 /= fmaxf(su2, 1e-9f);
    up3 /= fmaxf(su3, 1e-9f);

    const float4 r4 = *(const float4*)&resid[(size_t)q*CC + c0];
    float x0 = r4.x + up0, x1 = r4.y + up1, x2 = r4.z + up2, x3 = r4.w + up3;

    float s = x0 + x1 + x2 + x3;
#pragma unroll
    for (int o = 16; o; o >>= 1) s += __shfl_xor_sync(0xffffffffu, s, o);
    float mu = s * (1.f/128.f);
    float d0 = x0-mu, d1 = x1-mu, d2 = x2-mu, d3 = x3-mu;
    float vs = d0*d0 + d1*d1 + d2*d2 + d3*d3;
#pragma unroll
    for (int o = 16; o; o >>= 1) vs += __shfl_xor_sync(0xffffffffu, vs, o);
    float rstd = rsqrtf(vs * (1.f/128.f) + 1e-5f);

    const float4 gg = *(const float4*)&g1[c0];
    const float4 bb = *(const float4*)&b1[c0];
    float4 y;
    y.x = d0*rstd*gg.x + bb.x;
    y.y = d1*rstd*gg.y + bb.y;
    y.z = d2*rstd*gg.z + bb.z;
    y.w = d3*rstd*gg.w + bb.w;
    *(float4*)&out[(size_t)q*CC + c0] = y;
}

// ---------------- launch ----------------------------------------------------
extern "C" void kernel_launch(void* const* d_in, const int* in_sizes, int n_in,
                              void* d_out, int out_size)
{
    const float*         q_xyz  = (const float*)d_in[0];
    const float*         q_feat = (const float*)d_in[1];
    const float*         kv_xyz = (const float*)d_in[2];
    const float*         kv_feat= (const float*)d_in[3];
    const unsigned char* kv_pad = (const unsigned char*)d_in[4];
    const float* W_lin  = (const float*)d_in[5];
    const float* b_lin  = (const float*)d_in[6];
    const float* W_src  = (const float*)d_in[7];
    const float* W_dst  = (const float*)d_in[8];
    const float* W_attn = (const float*)d_in[9];
    const float* b_attn = (const float*)d_in[10];
    const float* ln1_g  = (const float*)d_in[11];
    const float* ln1_b  = (const float*)d_in[12];
    const float* W_ff1  = (const float*)d_in[13];
    const float* b_ff1  = (const float*)d_in[14];
    const float* W_ff2  = (const float*)d_in[15];
    const float* b_ff2  = (const float*)d_in[16];
    const float* ln2_g  = (const float*)d_in[17];
    const float* ln2_b  = (const float*)d_in[18];
    float* out = (float*)d_out;

    void *p_idx, *p_cnt, *p_sv, *p_P, *p_h, *p_wda, *p_wsv, *p_bsv;
    cudaGetSymbolAddress(&p_idx, g_idx);
    cudaGetSymbolAddress(&p_cnt, g_cnt);
    cudaGetSymbolAddress(&p_sv,  g_SV);
    cudaGetSymbolAddress(&p_P,   g_P);
    cudaGetSymbolAddress(&p_h,   g_h);
    cudaGetSymbolAddress(&p_wda, g_wda);
    cudaGetSymbolAddress(&p_wsv, g_wsv);
    cudaGetSymbolAddress(&p_bsv, g_bsv);
    int*   idx_p = (int*)p_idx;
    int*   cnt_p = (int*)p_cnt;
    float* sv_p  = (float*)p_sv;
    float* P_p   = (float*)p_P;
    float* h_p   = (float*)p_h;
    float* wda_p = (float*)p_wda;
    float* wsv_p = (float*)p_wsv;
    float* bsv_p = (float*)p_bsv;

    const int KNN_SMEM = 3*LL*4 + LL + 512*8*4*2;            // 86016
    const int SM128 = 2*(128*36 + 32*132)*4;                 // 70656
    const int SM64  = 2*(64*36  + 32*132)*4;                 // 52224
    cudaFuncSetAttribute(knn_kernel, cudaFuncAttributeMaxDynamicSharedMemorySize, KNN_SMEM);
    cudaFuncSetAttribute(gemm_mma<128,128,0>, cudaFuncAttributeMaxDynamicSharedMemorySize, SM128);
    cudaFuncSetAttribute(gemm_mma<128,128,1>, cudaFuncAttributeMaxDynamicSharedMemorySize, SM128);
    cudaFuncSetAttribute(gemm_mma<128,64,0>,  cudaFuncAttributeMaxDynamicSharedMemorySize, SM64);
    cudaFuncSetAttribute(gemm_mma<512,64,2>,  cudaFuncAttributeMaxDynamicSharedMemorySize, SM64);

    knn_kernel<<<dim3(BB, NN/128), 512, KNN_SMEM>>>(q_xyz, kv_xyz, kv_pad, idx_p, cnt_p);
    wprep_kernel<<<dim3(4, 2, 4), 256>>>(W_dst, W_src, W_attn, wda_p, wsv_p);
    copyk_kernel<<<dim3(16, 2), 256>>>(W_lin, b_lin, wsv_p, bsv_p);

    const int BL = BB*LL;   // 32768
    const int BN = BB*NN;   // 16384

    // [S0|V0|S1|V1] = kv_feat @ WSV + bSV   (both layers, one launch)
    gemm_mma<128,128,0><<<dim3(BL/128, 4), 256, SM128>>>(
        kv_feat, wsv_p, bsv_p, sv_p, 512, nullptr, nullptr, nullptr);

    for (int l = 0; l < 2; l++) {
        const size_t oCC = (size_t)l * CC * CC;
        const size_t oC  = (size_t)l * CC;
        const size_t oF1 = (size_t)l * CC * FFD;
        const size_t oF  = (size_t)l * FFD;
        const size_t oF2 = (size_t)l * FFD * CC;
        const float* in_l = (l == 0) ? q_feat : out;

        // P = in_l @ Wda + b_attn
        gemm_mma<128,64,0><<<dim3(BN/64, 1), 256, SM64>>>(
            in_l, wda_p + oCC, b_attn + oC, P_p, CC, nullptr, nullptr, nullptr);
        // attention gather/softmax + residual + LN1
        attn2_kernel<<<BN/8, 256>>>(
            P_p, sv_p + 256*l, sv_p + 256*l + 128, idx_p, cnt_p,
            in_l, out, ln1_g + oC, ln1_b + oC);
        // h = gelu(out @ W_ff1 + b_ff1)
        gemm_mma<128,128,1><<<dim3(BN/128, FFD/128), 256, SM128>>>(
            out, W_ff1 + oF1, b_ff1 + oF, h_p, FFD, nullptr, nullptr, nullptr);
        // out = LN2(out + h @ W_ff2 + b_ff2)
        gemm_mma<512,64,2><<<dim3(BN/64, 1), 256, SM64>>>(
            h_p, W_ff2 + oF2, b_ff2 + oC, out, CC, out, ln2_g + oC, ln2_b + oC);
    }
}

// round 5
// speedup vs baseline: 2.5360x; 1.0325x over previous
#include <cuda_runtime.h>
#include <math.h>
#include <stdint.h>

#define BB   8
#define NN   2048
#define LL   4096
#define CC   128
#define KNB  8
#define FFD  512
#define RR2  0.04f

// ---------------- scratch (device globals; no runtime allocation) ----------
__device__ int   g_idx [BB*NN*KNB];
__device__ int   g_cnt [BB*NN];
__device__ float g_SV [(size_t)BB*LL*512];  // [S0|V0|S1|V1] per kv row
__device__ float g_P  [(size_t)BB*NN*CC];
__device__ float g_h  [(size_t)BB*NN*FFD];
__device__ float g_wda[2*CC*CC];            // tf32-rounded
__device__ float g_wsv[CC*512];             // tf32-rounded [Wsa0|Wlin0|Wsa1|Wlin1]
__device__ float g_bsv[512];
__device__ float g_wf1[2*CC*FFD];           // tf32-rounded W_ff1
__device__ float g_wf2[2*FFD*CC];           // tf32-rounded W_ff2

__device__ __forceinline__ float to_tf32(float x) {
    float r;
    asm("cvt.rna.tf32.f32 %0, %1;" : "=f"(r) : "f"(x));
    return r;
}

__device__ __forceinline__ void mma_tf32(float* c, const uint32_t* a,
                                         uint32_t b0, uint32_t b1) {
    asm volatile(
        "mma.sync.aligned.m16n8k8.row.col.f32.tf32.tf32.f32 "
        "{%0,%1,%2,%3}, {%4,%5,%6,%7}, {%8,%9}, {%0,%1,%2,%3};"
        : "+f"(c[0]), "+f"(c[1]), "+f"(c[2]), "+f"(c[3])
        : "r"(a[0]), "r"(a[1]), "r"(a[2]), "r"(a[3]), "r"(b0), "r"(b1));
}

__device__ __forceinline__ void cp16(float* dst, const float* src) {
    uint32_t d = (uint32_t)__cvta_generic_to_shared(dst);
    asm volatile("cp.async.ca.shared.global [%0], [%1], 16;" :: "r"(d), "l"(src));
}

// ---------------- kNN radius search (4-way L split) -------------------------
__global__ __launch_bounds__(512) void knn_kernel(
    const float* __restrict__ qxyz, const float* __restrict__ kxyz,
    const unsigned char* __restrict__ kpad,
    int* __restrict__ gidx, int* __restrict__ gcnt)
{
    extern __shared__ float sh[];
    float* sx = sh;                                  // [3*LL]
    unsigned char* sp = (unsigned char*)(sh + 3*LL); // [LL]
    float* md = (float*)(sp + LL);                   // [512*8]
    int*   mi = (int*)(md + 512*8);                  // [512*8]

    const int tid = threadIdx.x;
    const int b = blockIdx.x;
    for (int i = tid; i < 3*LL; i += 512)
        sx[i] = kxyz[(size_t)b*3*LL + i];
    for (int i = tid; i < LL; i += 512)
        sp[i] = kpad[(size_t)b*LL + i];
    __syncthreads();

    const int qi   = tid & 127;
    const int part = tid >> 7;
    const int q = blockIdx.y * 128 + qi;
    const float qx = qxyz[((size_t)b*NN + q)*3 + 0];
    const float qy = qxyz[((size_t)b*NN + q)*3 + 1];
    const float qz = qxyz[((size_t)b*NN + q)*3 + 2];

    float bd[KNB]; int bi[KNB];
#pragma unroll
    for (int k = 0; k < KNB; k++) { bd[k] = 1e30f; bi[k] = 0; }

    const int j0 = part * (LL/4), j1 = j0 + LL/4;
    for (int j = j0; j < j1; j++) {
        float dx = sx[3*j+0] - qx;
        float dy = sx[3*j+1] - qy;
        float dz = sx[3*j+2] - qz;
        float d2 = fmaf(dx, dx, fmaf(dy, dy, dz*dz));
        if (d2 <= RR2 && d2 < bd[KNB-1] && !sp[j]) {
            float v = d2; int vi = j;
#pragma unroll
            for (int k = 0; k < KNB; k++) {
                if (v < bd[k]) {
                    float tf = bd[k]; bd[k] = v; v = tf;
                    int   ti = bi[k]; bi[k] = vi; vi = ti;
                }
            }
        }
    }
#pragma unroll
    for (int k = 0; k < KNB; k++) {
        md[(qi*4 + part)*8 + k] = bd[k];
        mi[(qi*4 + part)*8 + k] = bi[k];
    }
    __syncthreads();

    if (part == 0) {
        float fb[KNB]; int fi[KNB];
#pragma unroll
        for (int k = 0; k < KNB; k++) { fb[k] = 1e30f; fi[k] = 0; }
        for (int p = 0; p < 4; p++) {
            for (int k = 0; k < KNB; k++) {
                float v = md[(qi*4 + p)*8 + k];
                if (v >= fb[KNB-1]) break;   // lists sorted ascending
                int vi = mi[(qi*4 + p)*8 + k];
#pragma unroll
                for (int t = 0; t < KNB; t++) {
                    if (v < fb[t]) {
                        float tf = fb[t]; fb[t] = v; v = tf;
                        int   ti = fi[t]; fi[t] = vi; vi = ti;
                    }
                }
            }
        }
        int cnt = 0;
#pragma unroll
        for (int k = 0; k < KNB; k++) cnt += (fb[k] <= RR2) ? 1 : 0;
#pragma unroll
        for (int k = 0; k < KNB; k++)
            gidx[((size_t)b*NN + q)*KNB + k] = fi[k];
        gcnt[b*NN + q] = cnt;
    }
}

// ---------------- weight product prep (fp32 product, tf32-rounded store) ----
__global__ __launch_bounds__(256) void wprep_kernel(
    const float* __restrict__ Wd, const float* __restrict__ Ws,
    const float* __restrict__ Wa,
    float* __restrict__ Wda, float* __restrict__ Wsv)
{
    __shared__ float sA[64*132];
    const int p = blockIdx.z;
    const int layer = p >> 1;
    const float* A  = ((p & 1) ? Ws : Wd) + (size_t)layer*CC*CC;
    const float* Wm = Wa + (size_t)layer*CC*CC;
    float* O;
    int ldo;
    if (p & 1) { O = Wsv + 256*layer; ldo = 512; }
    else       { O = Wda + (size_t)layer*CC*CC; ldo = 128; }

    const int r0 = blockIdx.y * 64;
    const int n0 = blockIdx.x * 32;
    const int tid = threadIdx.x;

    for (int i = tid; i < 64*32; i += 256) {
        int row = i >> 5, c4 = (i & 31) * 4;
        float4 v = *(const float4*)&A[(size_t)(r0+row)*CC + c4];
        sA[row*132 + c4+0] = v.x;
        sA[row*132 + c4+1] = v.y;
        sA[row*132 + c4+2] = v.z;
        sA[row*132 + c4+3] = v.w;
    }
    __syncthreads();

    const int c  = n0 + (tid & 31);
    const int rr = (tid >> 5) * 8;
    float acc[8] = {0.f,0.f,0.f,0.f,0.f,0.f,0.f,0.f};
    for (int kk = 0; kk < 128; kk++) {
        float w = Wm[(size_t)kk*CC + c];
#pragma unroll
        for (int i = 0; i < 8; i++)
            acc[i] = fmaf(sA[(rr+i)*132 + kk], w, acc[i]);
    }
#pragma unroll
    for (int i = 0; i < 8; i++)
        O[(size_t)(r0+rr+i)*ldo + c] = to_tf32(acc[i]);
}

// ---------------- copy W_lin (tf32) into WSV + bias; stage W_ff tf32 --------
__global__ __launch_bounds__(256) void copyk_kernel(
    const float* __restrict__ Wlin, const float* __restrict__ blin,
    float* __restrict__ Wsv, float* __restrict__ bsv)
{
    const int l = blockIdx.y;
    for (int i = blockIdx.x*256 + threadIdx.x; i < CC*CC; i += gridDim.x*256) {
        int row = i >> 7, c = i & 127;
        Wsv[(size_t)row*512 + 256*l + 128 + c] = to_tf32(Wlin[(size_t)l*CC*CC + i]);
    }
    if (blockIdx.x == 0) {
        for (int i = threadIdx.x; i < 128; i += 256) {
            bsv[256*l + i]       = 0.f;
            bsv[256*l + 128 + i] = blin[l*CC + i];
        }
    }
}

__global__ __launch_bounds__(256) void wff_kernel(
    const float* __restrict__ W1, const float* __restrict__ W2,
    float* __restrict__ o1, float* __restrict__ o2)
{
    const int n = 2*CC*FFD;   // 131072 each
    for (int i = blockIdx.x*256 + threadIdx.x; i < n; i += gridDim.x*256) {
        o1[i] = to_tf32(W1[i]);
        o2[i] = to_tf32(W2[i]);
    }
}

// ---------------- tf32 tensor-core GEMM, cp.async double-buffered -----------
// B operand MUST already be tf32-rounded in global. CVTA=1 converts A at
// fragment load; CVTA=0 assumes A pre-rounded.
// EPI: 0 = (+bias), 1 = (+bias, exact GELU, store tf32-rounded),
//      2 = (+bias, +resid, LayerNorm)
template<int KD, int MT, int EPI, int CVTA>
__global__ __launch_bounds__(256, 2) void gemm_mma(
    const float* __restrict__ A, const float* __restrict__ W,
    const float* __restrict__ bias, float* __restrict__ Cout, int Ncols,
    const float* __restrict__ resid,
    const float* __restrict__ lng, const float* __restrict__ lnb)
{
    constexpr int MTC = MT / 64;
    constexpr int ASZ = MT * 36;
    constexpr int WSZ = 32 * 132;
    extern __shared__ float dynsm[];
    float* Abuf[2] = { dynsm,       dynsm + ASZ + WSZ };
    float* Wbuf[2] = { dynsm + ASZ, dynsm + 2*ASZ + WSZ };
    __shared__ float rs1[128], rs2[128];

    const int m0 = blockIdx.x * MT;
    const int n0 = blockIdx.y * 128;
    const int tid = threadIdx.x;
    const int lane = tid & 31, warp = tid >> 5;
    const int wm = (warp & 3) * (MT/4), wn = (warp >> 2) * 64;
    const int gID = lane >> 2, tig = lane & 3;

    if (EPI == 2 && tid < MT) { rs1[tid] = 0.f; rs2[tid] = 0.f; }

    float acc[MTC][8][4];
#pragma unroll
    for (int mt = 0; mt < MTC; mt++)
#pragma unroll
        for (int nt = 0; nt < 8; nt++)
#pragma unroll
            for (int c = 0; c < 4; c++) acc[mt][nt][c] = 0.f;

    auto issue = [&](int st, int kc) {
#pragma unroll
        for (int r = 0; r < MT/32; r++) {
            int id = tid + r*256;
            int row = id >> 3, c4 = (id & 7) * 4;
            cp16(&Abuf[st][row*36 + c4], &A[(size_t)(m0+row)*KD + kc + c4]);
        }
#pragma unroll
        for (int r = 0; r < 4; r++) {
            int id = tid + r*256;
            int row = id >> 5, c4 = (id & 31) * 4;
            cp16(&Wbuf[st][row*132 + c4], &W[(size_t)(kc+row)*Ncols + n0 + c4]);
        }
    };

    constexpr int NIT = KD / 32;
    issue(0, 0);
    asm volatile("cp.async.commit_group;");

    for (int it = 0; it < NIT; ++it) {
        if (it + 1 < NIT) {
            issue((it+1) & 1, (it+1)*32);
            asm volatile("cp.async.commit_group;");
            asm volatile("cp.async.wait_group 1;");
        } else {
            asm volatile("cp.async.wait_group 0;");
        }
        __syncthreads();
        const float* Ac = Abuf[it & 1];
        const float* Wc = Wbuf[it & 1];
#pragma unroll
        for (int k8 = 0; k8 < 4; k8++) {
            const int ka = k8 * 8;
            uint32_t a[MTC][4];
#pragma unroll
            for (int mt = 0; mt < MTC; mt++) {
                int r0 = wm + mt*16 + gID;
                float a0 = Ac[r0*36 + ka + tig];
                float a1 = Ac[(r0+8)*36 + ka + tig];
                float a2 = Ac[r0*36 + ka + tig + 4];
                float a3 = Ac[(r0+8)*36 + ka + tig + 4];
                if (CVTA) { a0=to_tf32(a0); a1=to_tf32(a1); a2=to_tf32(a2); a3=to_tf32(a3); }
                a[mt][0] = __float_as_uint(a0);
                a[mt][1] = __float_as_uint(a1);
                a[mt][2] = __float_as_uint(a2);
                a[mt][3] = __float_as_uint(a3);
            }
#pragma unroll
            for (int nt = 0; nt < 8; nt++) {
                int cb = wn + nt*8 + gID;
                uint32_t b0 = __float_as_uint(Wc[(ka+tig)*132 + cb]);
                uint32_t b1 = __float_as_uint(Wc[(ka+tig+4)*132 + cb]);
#pragma unroll
                for (int mt = 0; mt < MTC; mt++)
                    mma_tf32(acc[mt][nt], a[mt], b0, b1);
            }
        }
        if (it + 1 < NIT) __syncthreads();
    }

    if (EPI != 2) {
#pragma unroll
        for (int mt = 0; mt < MTC; mt++) {
            int row = m0 + wm + mt*16 + gID;
#pragma unroll
            for (int nt = 0; nt < 8; nt++) {
                int col = n0 + wn + nt*8 + 2*tig;
                float b0v = bias ? bias[col]   : 0.f;
                float b1v = bias ? bias[col+1] : 0.f;
                float v0 = acc[mt][nt][0] + b0v;
                float v1 = acc[mt][nt][1] + b1v;
                float v2 = acc[mt][nt][2] + b0v;
                float v3 = acc[mt][nt][3] + b1v;
                if (EPI == 1) {
                    v0 = to_tf32(0.5f*v0*(1.f + erff(v0*0.70710678118654752f)));
                    v1 = to_tf32(0.5f*v1*(1.f + erff(v1*0.70710678118654752f)));
                    v2 = to_tf32(0.5f*v2*(1.f + erff(v2*0.70710678118654752f)));
                    v3 = to_tf32(0.5f*v3*(1.f + erff(v3*0.70710678118654752f)));
                }
                *(float2*)&Cout[(size_t)row*Ncols + col]     = make_float2(v0, v1);
                *(float2*)&Cout[(size_t)(row+8)*Ncols + col] = make_float2(v2, v3);
            }
        }
    } else {
        // residual + LayerNorm epilogue (Ncols == 128, n0 == 0)
        float s1[MTC][2], s2[MTC][2];
#pragma unroll
        for (int mt = 0; mt < MTC; mt++) {
            s1[mt][0]=s1[mt][1]=s2[mt][0]=s2[mt][1]=0.f;
            int row = m0 + wm + mt*16 + gID;
#pragma unroll
            for (int nt = 0; nt < 8; nt++) {
                int col = wn + nt*8 + 2*tig;
                float b0v = bias[col], b1v = bias[col+1];
                float x0 = acc[mt][nt][0] + b0v + resid[(size_t)row*128 + col];
                float x1 = acc[mt][nt][1] + b1v + resid[(size_t)row*128 + col+1];
                float x2 = acc[mt][nt][2] + b0v + resid[(size_t)(row+8)*128 + col];
                float x3 = acc[mt][nt][3] + b1v + resid[(size_t)(row+8)*128 + col+1];
                acc[mt][nt][0]=x0; acc[mt][nt][1]=x1; acc[mt][nt][2]=x2; acc[mt][nt][3]=x3;
                s1[mt][0] += x0 + x1;       s1[mt][1] += x2 + x3;
                s2[mt][0] += x0*x0 + x1*x1; s2[mt][1] += x2*x2 + x3*x3;
            }
        }
#pragma unroll
        for (int mt = 0; mt < MTC; mt++)
#pragma unroll
            for (int h = 0; h < 2; h++) {
                s1[mt][h] += __shfl_xor_sync(0xffffffffu, s1[mt][h], 1);
                s1[mt][h] += __shfl_xor_sync(0xffffffffu, s1[mt][h], 2);
                s2[mt][h] += __shfl_xor_sync(0xffffffffu, s2[mt][h], 1);
                s2[mt][h] += __shfl_xor_sync(0xffffffffu, s2[mt][h], 2);
            }
        if (tig == 0) {
#pragma unroll
            for (int mt = 0; mt < MTC; mt++)
#pragma unroll
                for (int h = 0; h < 2; h++) {
                    int lr = wm + mt*16 + gID + h*8;
                    atomicAdd(&rs1[lr], s1[mt][h]);
                    atomicAdd(&rs2[lr], s2[mt][h]);
                }
        }
        __syncthreads();
#pragma unroll
        for (int mt = 0; mt < MTC; mt++) {
            int lr = wm + mt*16 + gID;
            float mu0 = rs1[lr]   * (1.f/128.f);
            float mu1 = rs1[lr+8] * (1.f/128.f);
            float rstd0 = rsqrtf(rs2[lr]  *(1.f/128.f) - mu0*mu0 + 1e-5f);
            float rstd1 = rsqrtf(rs2[lr+8]*(1.f/128.f) - mu1*mu1 + 1e-5f);
            int row = m0 + lr;
#pragma unroll
            for (int nt = 0; nt < 8; nt++) {
                int col = wn + nt*8 + 2*tig;
                float g0 = lng[col], g1 = lng[col+1];
                float bb0 = lnb[col], bb1 = lnb[col+1];
                float y0 = (acc[mt][nt][0]-mu0)*rstd0*g0 + bb0;
                float y1 = (acc[mt][nt][1]-mu0)*rstd0*g1 + bb1;
                float y2 = (acc[mt][nt][2]-mu1)*rstd1*g0 + bb0;
                float y3 = (acc[mt][nt][3]-mu1)*rstd1*g1 + bb1;
                *(float2*)&Cout[(size_t)row*128 + col]     = make_float2(y0, y1);
                *(float2*)&Cout[(size_t)(row+8)*128 + col] = make_float2(y2, y3);
            }
        }
    }
}

// ---------------- light attention: gather + softmax + residual + LN ---------
__global__ __launch_bounds__(256) void attn2_kernel(
    const float* __restrict__ P, const float* __restrict__ S,
    const float* __restrict__ V, const int* __restrict__ gidx,
    const int* __restrict__ gcnt,
    const float* __restrict__ resid, float* __restrict__ out,
    const float* __restrict__ g1, const float* __restrict__ b1)
{
    const int warp = threadIdx.x >> 5, lane = threadIdx.x & 31;
    const int q = blockIdx.x * 8 + warp;       // global over B*N
    const int b = q / NN;
    const int c0 = lane * 4;

    const float4 p4 = *(const float4*)&P[(size_t)q*CC + c0];
    const int kcnt = gcnt[q];
    int nid[KNB];
#pragma unroll
    for (int k = 0; k < KNB; k++) nid[k] = gidx[(size_t)q*KNB + k];

    float4 lg[KNB];
    float mx0 = -1e30f, mx1 = -1e30f, mx2 = -1e30f, mx3 = -1e30f;
#pragma unroll
    for (int k = 0; k < KNB; k++) {
        if (k < kcnt) {
            const float4 s4 = *(const float4*)&S[((size_t)b*LL + nid[k])*512 + c0];
            float4 l;
            l.x = fmaxf(p4.x - s4.x, 0.f);
            l.y = fmaxf(p4.y - s4.y, 0.f);
            l.z = fmaxf(p4.z - s4.z, 0.f);
            l.w = fmaxf(p4.w - s4.w, 0.f);
            lg[k] = l;
            mx0 = fmaxf(mx0, l.x); mx1 = fmaxf(mx1, l.y);
            mx2 = fmaxf(mx2, l.z); mx3 = fmaxf(mx3, l.w);
        }
    }

    float su0=0.f, su1=0.f, su2=0.f, su3=0.f;
    float up0=0.f, up1=0.f, up2=0.f, up3=0.f;
#pragma unroll
    for (int k = 0; k < KNB; k++) {
        if (k < kcnt) {
            const float4 v4 = *(const float4*)&V[((size_t)b*LL + nid[k])*512 + c0];
            float w0 = expf(lg[k].x - mx0);
            float w1 = expf(lg[k].y - mx1);
            float w2 = expf(lg[k].z - mx2);
            float w3 = expf(lg[k].w - mx3);
            su0 += w0; su1 += w1; su2 += w2; su3 += w3;
            up0 = fmaf(w0, v4.x, up0);
            up1 = fmaf(w1, v4.y, up1);
            up2 = fmaf(w2, v4.z, up2);
            up3 = fmaf(w3, v4.w, up3);
        }
    }
    up0 /= fmaxf(su0, 1e-9f);
    up1 /= fmaxf(su1, 1e-9f);
    up2 /= fmaxf(su2, 1e-9f);
    up3 /= fmaxf(su3, 1e-9f);

    const float4 r4 = *(const float4*)&resid[(size_t)q*CC + c0];
    float x0 = r4.x + up0, x1 = r4.y + up1, x2 = r4.z + up2, x3 = r4.w + up3;

    float s = x0 + x1 + x2 + x3;
#pragma unroll
    for (int o = 16; o; o >>= 1) s += __shfl_xor_sync(0xffffffffu, s, o);
    float mu = s * (1.f/128.f);
    float d0 = x0-mu, d1 = x1-mu, d2 = x2-mu, d3 = x3-mu;
    float vs = d0*d0 + d1*d1 + d2*d2 + d3*d3;
#pragma unroll
    for (int o = 16; o; o >>= 1) vs += __shfl_xor_sync(0xffffffffu, vs, o);
    float rstd = rsqrtf(vs * (1.f/128.f) + 1e-5f);

    const float4 gg = *(const float4*)&g1[c0];
    const float4 bb = *(const float4*)&b1[c0];
    float4 y;
    y.x = d0*rstd*gg.x + bb.x;
    y.y = d1*rstd*gg.y + bb.y;
    y.z = d2*rstd*gg.z + bb.z;
    y.w = d3*rstd*gg.w + bb.w;
    *(float4*)&out[(size_t)q*CC + c0] = y;
}

// ---------------- launch ----------------------------------------------------
extern "C" void kernel_launch(void* const* d_in, const int* in_sizes, int n_in,
                              void* d_out, int out_size)
{
    const float*         q_xyz  = (const float*)d_in[0];
    const float*         q_feat = (const float*)d_in[1];
    const float*         kv_xyz = (const float*)d_in[2];
    const float*         kv_feat= (const float*)d_in[3];
    const unsigned char* kv_pad = (const unsigned char*)d_in[4];
    const float* W_lin  = (const float*)d_in[5];
    const float* b_lin  = (const float*)d_in[6];
    const float* W_src  = (const float*)d_in[7];
    const float* W_dst  = (const float*)d_in[8];
    const float* W_attn = (const float*)d_in[9];
    const float* b_attn = (const float*)d_in[10];
    const float* ln1_g  = (const float*)d_in[11];
    const float* ln1_b  = (const float*)d_in[12];
    const float* W_ff1  = (const float*)d_in[13];
    const float* b_ff1  = (const float*)d_in[14];
    const float* W_ff2  = (const float*)d_in[15];
    const float* b_ff2  = (const float*)d_in[16];
    const float* ln2_g  = (const float*)d_in[17];
    const float* ln2_b  = (const float*)d_in[18];
    float* out = (float*)d_out;

    void *p_idx, *p_cnt, *p_sv, *p_P, *p_h, *p_wda, *p_wsv, *p_bsv, *p_wf1, *p_wf2;
    cudaGetSymbolAddress(&p_idx, g_idx);
    cudaGetSymbolAddress(&p_cnt, g_cnt);
    cudaGetSymbolAddress(&p_sv,  g_SV);
    cudaGetSymbolAddress(&p_P,   g_P);
    cudaGetSymbolAddress(&p_h,   g_h);
    cudaGetSymbolAddress(&p_wda, g_wda);
    cudaGetSymbolAddress(&p_wsv, g_wsv);
    cudaGetSymbolAddress(&p_bsv, g_bsv);
    cudaGetSymbolAddress(&p_wf1, g_wf1);
    cudaGetSymbolAddress(&p_wf2, g_wf2);
    int*   idx_p = (int*)p_idx;
    int*   cnt_p = (int*)p_cnt;
    float* sv_p  = (float*)p_sv;
    float* P_p   = (float*)p_P;
    float* h_p   = (float*)p_h;
    float* wda_p = (float*)p_wda;
    float* wsv_p = (float*)p_wsv;
    float* bsv_p = (float*)p_bsv;
    float* wf1_p = (float*)p_wf1;
    float* wf2_p = (float*)p_wf2;

    const int KNN_SMEM = 3*LL*4 + LL + 512*8*4*2;            // 86016
    const int SM128 = 2*(128*36 + 32*132)*4;                 // 70656
    const int SM64  = 2*(64*36  + 32*132)*4;                 // 52224
    cudaFuncSetAttribute(knn_kernel, cudaFuncAttributeMaxDynamicSharedMemorySize, KNN_SMEM);
    cudaFuncSetAttribute(gemm_mma<128,128,0,1>, cudaFuncAttributeMaxDynamicSharedMemorySize, SM128);
    cudaFuncSetAttribute(gemm_mma<128,128,1,1>, cudaFuncAttributeMaxDynamicSharedMemorySize, SM128);
    cudaFuncSetAttribute(gemm_mma<128,64,0,1>,  cudaFuncAttributeMaxDynamicSharedMemorySize, SM64);
    cudaFuncSetAttribute(gemm_mma<512,64,2,0>,  cudaFuncAttributeMaxDynamicSharedMemorySize, SM64);

    knn_kernel<<<dim3(BB, NN/128), 512, KNN_SMEM>>>(q_xyz, kv_xyz, kv_pad, idx_p, cnt_p);
    wprep_kernel<<<dim3(4, 2, 4), 256>>>(W_dst, W_src, W_attn, wda_p, wsv_p);
    copyk_kernel<<<dim3(16, 2), 256>>>(W_lin, b_lin, wsv_p, bsv_p);
    wff_kernel<<<128, 256>>>(W_ff1, W_ff2, wf1_p, wf2_p);

    const int BL = BB*LL;   // 32768
    const int BN = BB*NN;   // 16384

    // [S0|V0|S1|V1] = kv_feat @ WSV + bSV   (both layers, one launch)
    gemm_mma<128,128,0,1><<<dim3(BL/128, 4), 256, SM128>>>(
        kv_feat, wsv_p, bsv_p, sv_p, 512, nullptr, nullptr, nullptr);

    for (int l = 0; l < 2; l++) {
        const size_t oCC = (size_t)l * CC * CC;
        const size_t oC  = (size_t)l * CC;
        const size_t oF1 = (size_t)l * CC * FFD;
        const size_t oF  = (size_t)l * FFD;
        const size_t oF2 = (size_t)l * FFD * CC;
        const float* in_l = (l == 0) ? q_feat : out;

        // P = in_l @ Wda + b_attn
        gemm_mma<128,64,0,1><<<dim3(BN/64, 1), 256, SM64>>>(
            in_l, wda_p + oCC, b_attn + oC, P_p, CC, nullptr, nullptr, nullptr);
        // attention gather/softmax + residual + LN1
        attn2_kernel<<<BN/8, 256>>>(
            P_p, sv_p + 256*l, sv_p + 256*l + 128, idx_p, cnt_p,
            in_l, out, ln1_g + oC, ln1_b + oC);
        // h = gelu(out @ W_ff1 + b_ff1), stored tf32-rounded
        gemm_mma<128,128,1,1><<<dim3(BN/128, FFD/128), 256, SM128>>>(
            out, wf1_p + oF1, b_ff1 + oF, h_p, FFD, nullptr, nullptr, nullptr);
        // out = LN2(out + h @ W_ff2 + b_ff2)   (h pre-rounded -> CVTA=0)
        gemm_mma<512,64,2,0><<<dim3(BN/64, 1), 256, SM64>>>(
            h_p, wf2_p + oF2, b_ff2 + oC, out, CC, out, ln2_g + oC, ln2_b + oC);
    }
}